// round 3
// baseline (speedup 1.0000x reference)
#include <cuda_runtime.h>
#include <math.h>

#define BB 8
#define TT 1024
#define DD 512
#define HH 8
#define FF 2048
#define MM (BB*TT)   // 8192 rows

// ---------------- scratch (allocation-free: __device__ globals) ----------------
__device__ float g_h[MM*DD];      // LN(x)
__device__ float g_q[MM*DD];
__device__ float g_k[MM*DD];
__device__ float g_v[MM*DD];
__device__ float g_attn[MM*DD];   // attention output (pre-residual)
__device__ float g_a[MM*DD];      // LN1(attn + x)
__device__ float g_f1[MM*FF];     // relu(a@W1+b1)
__device__ float g_f2[MM*DD];     // f1@W2+b2

// ---------------- LayerNorm (optionally fused residual add) ----------------
// out[row] = LN(in1[row] + in2[row]) * g + b   (in2 may be null)
__global__ __launch_bounds__(256) void ln_kernel(
    const float* __restrict__ in1, const float* __restrict__ in2,
    const float* __restrict__ gam, const float* __restrict__ bet,
    float* __restrict__ out)
{
    int row = blockIdx.x;
    int t = threadIdx.x;
    const float* p1 = in1 + (size_t)row * DD;
    float v0 = p1[t];
    float v1 = p1[t + 256];
    if (in2) {
        const float* p2 = in2 + (size_t)row * DD;
        v0 += p2[t];
        v1 += p2[t + 256];
    }
    __shared__ float red[8];
    float s = v0 + v1;
    #pragma unroll
    for (int o = 16; o > 0; o >>= 1) s += __shfl_xor_sync(0xffffffffu, s, o);
    if ((t & 31) == 0) red[t >> 5] = s;
    __syncthreads();
    float tot = 0.f;
    #pragma unroll
    for (int i = 0; i < 8; i++) tot += red[i];
    float mu = tot * (1.0f / DD);
    float d0 = v0 - mu, d1 = v1 - mu;
    s = d0 * d0 + d1 * d1;
    #pragma unroll
    for (int o = 16; o > 0; o >>= 1) s += __shfl_xor_sync(0xffffffffu, s, o);
    __syncthreads();                      // reads of red[] done before overwrite
    if ((t & 31) == 0) red[t >> 5] = s;
    __syncthreads();
    tot = 0.f;
    #pragma unroll
    for (int i = 0; i < 8; i++) tot += red[i];
    float r = rsqrtf(tot * (1.0f / DD) + 1e-3f);
    out[(size_t)row * DD + t]       = d0 * r * gam[t]       + bet[t];
    out[(size_t)row * DD + t + 256] = d1 * r * gam[t + 256] + bet[t + 256];
}

// ---------------- SGEMM: C[M,N] = A[M,K] @ W[K,N] + bias (+relu) ----------------
// 128x128 block tile, BK=16, 256 threads, 8x8 register microtile.
// M,N,K all multiples of 128/128/16 for this problem -> no bounds checks.
template<bool RELU>
__global__ __launch_bounds__(256) void sgemm_kernel(
    const float* __restrict__ A, const float* __restrict__ Bw,
    const float* __restrict__ bias, float* __restrict__ C,
    int M, int N, int K)
{
    __shared__ __align__(16) float As[16][128];   // transposed: As[k][m]
    __shared__ __align__(16) float Bs[16][128];   // Bs[k][n]
    int brow = blockIdx.y * 128;
    int bcol = blockIdx.x * 128;
    int t = threadIdx.x;
    int ty = t >> 4, tx = t & 15;

    float acc[8][8];
    #pragma unroll
    for (int i = 0; i < 8; i++)
        #pragma unroll
        for (int j = 0; j < 8; j++) acc[i][j] = 0.f;

    for (int k0 = 0; k0 < K; k0 += 16) {
        #pragma unroll
        for (int i = 0; i < 2; i++) {
            int idx = t + i * 256;          // 0..511 float4 slots of A tile
            int r = idx >> 2, c = idx & 3;
            float4 a4 = *(const float4*)(A + (size_t)(brow + r) * K + k0 + c * 4);
            As[c*4+0][r] = a4.x; As[c*4+1][r] = a4.y;
            As[c*4+2][r] = a4.z; As[c*4+3][r] = a4.w;
        }
        #pragma unroll
        for (int i = 0; i < 2; i++) {
            int idx = t + i * 256;          // 0..511 float4 slots of B tile
            int r = idx >> 5, c = idx & 31;
            *(float4*)&Bs[r][c*4] = *(const float4*)(Bw + (size_t)(k0 + r) * N + bcol + c * 4);
        }
        __syncthreads();
        #pragma unroll
        for (int k = 0; k < 16; k++) {
            float af[8], bf[8];
            *(float4*)&af[0] = *(float4*)&As[k][ty*8];
            *(float4*)&af[4] = *(float4*)&As[k][ty*8+4];
            *(float4*)&bf[0] = *(float4*)&Bs[k][tx*8];
            *(float4*)&bf[4] = *(float4*)&Bs[k][tx*8+4];
            #pragma unroll
            for (int i = 0; i < 8; i++)
                #pragma unroll
                for (int j = 0; j < 8; j++)
                    acc[i][j] += af[i] * bf[j];
        }
        __syncthreads();
    }

    float bv[8];
    *(float4*)&bv[0] = *(const float4*)(bias + bcol + tx*8);
    *(float4*)&bv[4] = *(const float4*)(bias + bcol + tx*8 + 4);
    #pragma unroll
    for (int i = 0; i < 8; i++) {
        float o[8];
        #pragma unroll
        for (int j = 0; j < 8; j++) {
            float v = acc[i][j] + bv[j];
            if (RELU) v = fmaxf(v, 0.f);
            o[j] = v;
        }
        float* cp = C + (size_t)(brow + ty*8 + i) * N + bcol + tx*8;
        *(float4*)cp       = *(float4*)&o[0];
        *(float4*)(cp + 4) = *(float4*)&o[4];
    }
}

// ---------------- Flash attention (fp32, online softmax) ----------------
// Grid: (qtile=16, head=8, batch=8). 256 threads = 16(ty) x 16(tx).
// Tile: 64 queries x 64 keys, DK=64. Thread microtile 4x4 with
// rows R_i = ty*4+i, cols/dims C_j = tx + 16*j (interleaved => conflict-free
// LDS with row pitch 65 floats).
#define APITCH 65
#define ATTN_SMEM (4 * 64 * APITCH * (int)sizeof(float))

__global__ __launch_bounds__(256) void attn_kernel(
    const float* __restrict__ Q, const float* __restrict__ Kb,
    const float* __restrict__ Vb, const float* __restrict__ mask,
    float* __restrict__ O)
{
    extern __shared__ float sm[];
    float* Qs = sm;                   // 64 x 65
    float* Ks = Qs + 64 * APITCH;     // 64 x 65
    float* Vs = Ks + 64 * APITCH;     // 64 x 65
    float* Ps = Vs + 64 * APITCH;     // 64 x 65

    int b = blockIdx.z, h = blockIdx.y, qt = blockIdx.x;
    int t = threadIdx.x;
    int ty = t >> 4, tx = t & 15;

    const float* qptr  = Q  + ((size_t)(b * TT) + qt * 64) * DD + h * 64;
    const float* kptr0 = Kb + (size_t)(b * TT) * DD + h * 64;
    const float* vptr0 = Vb + (size_t)(b * TT) * DD + h * 64;
    const float* mptr  = mask + ((size_t)b * TT + qt * 64) * TT;

    #pragma unroll
    for (int i = 0; i < 4; i++) {
        int idx = t + i * 256;        // 1024 float4 slots: 64 rows x 16
        int r = idx >> 4, c = idx & 15;
        float4 v = *(const float4*)(qptr + (size_t)r * DD + c * 4);
        float* dst = Qs + r * APITCH + c * 4;
        dst[0] = v.x; dst[1] = v.y; dst[2] = v.z; dst[3] = v.w;
    }

    float m[4], l[4], acc[4][4];
    #pragma unroll
    for (int i = 0; i < 4; i++) {
        m[i] = -1e30f; l[i] = 0.f;
        #pragma unroll
        for (int j = 0; j < 4; j++) acc[i][j] = 0.f;
    }
    __syncthreads();

    for (int kt = 0; kt < TT / 64; kt++) {
        #pragma unroll
        for (int i = 0; i < 4; i++) {
            int idx = t + i * 256;
            int r = idx >> 4, c = idx & 15;
            float4 kv = *(const float4*)(kptr0 + (size_t)(kt * 64 + r) * DD + c * 4);
            float* kd = Ks + r * APITCH + c * 4;
            kd[0] = kv.x; kd[1] = kv.y; kd[2] = kv.z; kd[3] = kv.w;
            float4 vv = *(const float4*)(vptr0 + (size_t)(kt * 64 + r) * DD + c * 4);
            float* vd = Vs + r * APITCH + c * 4;
            vd[0] = vv.x; vd[1] = vv.y; vd[2] = vv.z; vd[3] = vv.w;
        }
        __syncthreads();

        // S = Q K^T (4x4 per thread)
        float s[4][4];
        #pragma unroll
        for (int i = 0; i < 4; i++)
            #pragma unroll
            for (int j = 0; j < 4; j++) s[i][j] = 0.f;
        #pragma unroll 8
        for (int d = 0; d < 64; d++) {
            float qv[4], kv[4];
            #pragma unroll
            for (int i = 0; i < 4; i++) qv[i] = Qs[(ty*4 + i) * APITCH + d];
            #pragma unroll
            for (int j = 0; j < 4; j++) kv[j] = Ks[(tx + 16*j) * APITCH + d];
            #pragma unroll
            for (int i = 0; i < 4; i++)
                #pragma unroll
                for (int j = 0; j < 4; j++)
                    s[i][j] += qv[i] * kv[j];
        }

        // scale + additive mask + online softmax (row reductions over 16 tx lanes)
        #pragma unroll
        for (int i = 0; i < 4; i++) {
            int qrow = ty*4 + i;
            float rm = -1e30f;
            #pragma unroll
            for (int j = 0; j < 4; j++) {
                float mk = mptr[(size_t)qrow * TT + kt * 64 + tx + 16*j];
                float sv = s[i][j] * 0.125f + (mk - 1.0f) * 1e9f;
                s[i][j] = sv;
                rm = fmaxf(rm, sv);
            }
            #pragma unroll
            for (int o = 8; o > 0; o >>= 1)
                rm = fmaxf(rm, __shfl_xor_sync(0xffffffffu, rm, o));
            float mn = fmaxf(m[i], rm);
            float corr = __expf(m[i] - mn);
            float rl = 0.f;
            #pragma unroll
            for (int j = 0; j < 4; j++) {
                float p = __expf(s[i][j] - mn);
                s[i][j] = p;
                rl += p;
            }
            #pragma unroll
            for (int o = 8; o > 0; o >>= 1)
                rl += __shfl_xor_sync(0xffffffffu, rl, o);
            l[i] = l[i] * corr + rl;
            m[i] = mn;
            #pragma unroll
            for (int j = 0; j < 4; j++) acc[i][j] *= corr;
            #pragma unroll
            for (int j = 0; j < 4; j++) Ps[qrow * APITCH + tx + 16*j] = s[i][j];
        }
        __syncthreads();

        // O += P @ V (4x4 per thread, dims D_j = tx + 16*j)
        #pragma unroll 8
        for (int col = 0; col < 64; col++) {
            float pv[4], vv[4];
            #pragma unroll
            for (int i = 0; i < 4; i++) pv[i] = Ps[(ty*4 + i) * APITCH + col];
            #pragma unroll
            for (int j = 0; j < 4; j++) vv[j] = Vs[col * APITCH + tx + 16*j];
            #pragma unroll
            for (int i = 0; i < 4; i++)
                #pragma unroll
                for (int j = 0; j < 4; j++)
                    acc[i][j] += pv[i] * vv[j];
        }
        __syncthreads();
    }

    float* optr = O + ((size_t)(b * TT) + qt * 64) * DD + h * 64;
    #pragma unroll
    for (int i = 0; i < 4; i++) {
        float inv = 1.0f / l[i];
        #pragma unroll
        for (int j = 0; j < 4; j++)
            optr[(size_t)(ty*4 + i) * DD + tx + 16*j] = acc[i][j] * inv;
    }
}

// ---------------- launch ----------------
extern "C" void kernel_launch(void* const* d_in, const int* in_sizes, int n_in,
                              void* d_out, int out_size)
{
    const float* x       = (const float*)d_in[0];
    const float* mask    = (const float*)d_in[1];
    const float* ln_in_g = (const float*)d_in[2];
    const float* ln_in_b = (const float*)d_in[3];
    const float* Wq = (const float*)d_in[4];
    const float* bq = (const float*)d_in[5];
    const float* Wk = (const float*)d_in[6];
    const float* bk = (const float*)d_in[7];
    const float* Wv = (const float*)d_in[8];
    const float* bv = (const float*)d_in[9];
    const float* ln1_g = (const float*)d_in[10];
    const float* ln1_b = (const float*)d_in[11];
    const float* W1 = (const float*)d_in[12];
    const float* b1 = (const float*)d_in[13];
    const float* W2 = (const float*)d_in[14];
    const float* b2 = (const float*)d_in[15];
    const float* ln2_g = (const float*)d_in[16];
    const float* ln2_b = (const float*)d_in[17];
    float* out = (float*)d_out;

    float *hbuf, *qbuf, *kbuf, *vbuf, *attnbuf, *abuf, *f1buf, *f2buf;
    cudaGetSymbolAddress((void**)&hbuf,    g_h);
    cudaGetSymbolAddress((void**)&qbuf,    g_q);
    cudaGetSymbolAddress((void**)&kbuf,    g_k);
    cudaGetSymbolAddress((void**)&vbuf,    g_v);
    cudaGetSymbolAddress((void**)&attnbuf, g_attn);
    cudaGetSymbolAddress((void**)&abuf,    g_a);
    cudaGetSymbolAddress((void**)&f1buf,   g_f1);
    cudaGetSymbolAddress((void**)&f2buf,   g_f2);

    cudaFuncSetAttribute(attn_kernel,
                         cudaFuncAttributeMaxDynamicSharedMemorySize, ATTN_SMEM);

    // 1. h = LN(x)
    ln_kernel<<<MM, 256>>>(x, nullptr, ln_in_g, ln_in_b, hbuf);

    // 2. q/k/v = h @ W* + b*
    dim3 g512(DD / 128, MM / 128);
    sgemm_kernel<false><<<g512, 256>>>(hbuf, Wq, bq, qbuf, MM, DD, DD);
    sgemm_kernel<false><<<g512, 256>>>(hbuf, Wk, bk, kbuf, MM, DD, DD);
    sgemm_kernel<false><<<g512, 256>>>(hbuf, Wv, bv, vbuf, MM, DD, DD);

    // 3. masked flash attention
    attn_kernel<<<dim3(TT / 64, HH, BB), 256, ATTN_SMEM>>>(qbuf, kbuf, vbuf, mask, attnbuf);

    // 4. a = LN1(attn + x)
    ln_kernel<<<MM, 256>>>(attnbuf, x, ln1_g, ln1_b, abuf);

    // 5. FFN
    sgemm_kernel<true ><<<dim3(FF / 128, MM / 128), 256>>>(abuf, W1, b1, f1buf, MM, FF, DD);
    sgemm_kernel<false><<<g512, 256>>>(f1buf, W2, b2, f2buf, MM, DD, FF);

    // 6. out = LN2(f + a)
    ln_kernel<<<MM, 256>>>(f2buf, abuf, ln2_g, ln2_b, out);
}

// round 6
// speedup vs baseline: 1.8154x; 1.8154x over previous
#include <cuda_runtime.h>
#include <cstdint>
#include <math.h>

#define BB 8
#define TT 1024
#define DD 512
#define HH 8
#define FF 2048
#define MM (BB*TT)   // 8192 rows
#define NQKV (3*DD)  // 1536

// ---------------- scratch (allocation-free: __device__ globals) ----------------
__device__ float g_h[MM*DD];        // LN(x), tf32-rounded
__device__ float g_qkv[MM*NQKV];    // fused QKV output [M,1536]
__device__ float g_attn[MM*DD];     // attention output (pre-residual)
__device__ float g_a[MM*DD];        // LN1(attn + x), tf32-rounded
__device__ float g_f1[MM*FF];       // relu(a@W1+b1), tf32-rounded
__device__ float g_f2[MM*DD];       // f1@W2+b2
__device__ float g_Wqkvt[NQKV*DD];  // [1536,512] tf32 (rows: q|k|v), transposed
__device__ float g_W1t[FF*DD];      // [2048,512] tf32
__device__ float g_W2t[DD*FF];      // [512,2048] tf32
__device__ float g_bqkv[NQKV];

// ---------------- helpers ----------------
__device__ __forceinline__ uint32_t s2u(const void* p) {
    uint32_t a;
    asm("{ .reg .u64 t; cvta.to.shared.u64 t, %1; cvt.u32.u64 %0, t; }" : "=r"(a) : "l"(p));
    return a;
}
__device__ __forceinline__ float cvt_tf32f(float x) {
    uint32_t r; asm("cvt.rna.tf32.f32 %0, %1;" : "=r"(r) : "f"(x));
    return __uint_as_float(r);
}
__device__ __forceinline__ void cp_async16(uint32_t saddr, const void* gaddr) {
    asm volatile("cp.async.ca.shared.global [%0], [%1], 16;" :: "r"(saddr), "l"(gaddr));
}
__device__ __forceinline__ void cp_commit() {
    asm volatile("cp.async.commit_group;" ::: "memory");
}
__device__ __forceinline__ void cp_wait1() {
    asm volatile("cp.async.wait_group 1;" ::: "memory");
}
__device__ __forceinline__ void cp_wait0() {
    asm volatile("cp.async.wait_group 0;" ::: "memory");
}
// D = A(row,m16k8 tf32) * B(col,k8n8 tf32) + D, fp32 accum
__device__ __forceinline__ void mma_tf32(float* c, const uint32_t* a, const uint32_t* b) {
    asm volatile(
        "mma.sync.aligned.m16n8k8.row.col.f32.tf32.tf32.f32 "
        "{%0,%1,%2,%3}, {%4,%5,%6,%7}, {%8,%9}, {%0,%1,%2,%3};"
        : "+f"(c[0]), "+f"(c[1]), "+f"(c[2]), "+f"(c[3])
        : "r"(a[0]), "r"(a[1]), "r"(a[2]), "r"(a[3]), "r"(b[0]), "r"(b[1]));
}

// ---------------- weight transpose + tf32(rna) convert: W[R,N] -> Wt[N,R] -------
__global__ void transpose_tf32(const float* __restrict__ W, float* __restrict__ Wt,
                               int R, int N) {
    __shared__ float tile[32][33];
    int rb = blockIdx.y * 32, nb = blockIdx.x * 32;
    int tx = threadIdx.x, ty = threadIdx.y;   // 32 x 8
    #pragma unroll
    for (int i = 0; i < 32; i += 8)
        tile[ty + i][tx] = W[(size_t)(rb + ty + i) * N + nb + tx];
    __syncthreads();
    #pragma unroll
    for (int i = 0; i < 32; i += 8)
        Wt[(size_t)(nb + ty + i) * R + rb + tx] = cvt_tf32f(tile[tx][ty + i]);
}

__global__ void concat_bias(const float* __restrict__ bq, const float* __restrict__ bk,
                            const float* __restrict__ bv, float* __restrict__ o) {
    int t = blockIdx.x * 256 + threadIdx.x;
    if (t < NQKV)
        o[t] = t < 512 ? bq[t] : (t < 1024 ? bk[t - 512] : bv[t - 1024]);
}

// ---------------- tf32 mma.sync GEMM: C[M,N] = A[M,K] @ Bt[N,K]^T + bias --------
// 128x128 CTA tile, BK=32, 2-stage cp.async pipeline, 256 threads (8 warps 2x4).
// SMEM pitch 36 floats => every fragment LDS is bank-conflict-free.
#define KC 32
#define PITCH 36
#define STG_FLOATS (2 * 128 * PITCH)      // A + B per stage = 9216 floats
#define GEMM_SMEM (2 * STG_FLOATS * (int)sizeof(float))   // 73728 B

template<bool RELU, bool CVT>
__global__ __launch_bounds__(256)
void tc_gemm(const float* __restrict__ A, const float* __restrict__ Bt,
             const float* __restrict__ bias, float* __restrict__ C,
             int M, int N, int K)
{
    extern __shared__ float sm[];
    uint32_t sbase = s2u(sm);

    int t = threadIdx.x;
    int wid = t >> 5, lane = t & 31;
    int g = lane >> 2, tg = lane & 3;          // groupID / thread-in-group
    int wm = wid & 1, wn = wid >> 1;           // warp tile: rows wm*64, cols wn*32
    int brow = blockIdx.y * 128, bcol = blockIdx.x * 128;

    float acc[4][4][4];
    #pragma unroll
    for (int i = 0; i < 4; i++)
        #pragma unroll
        for (int j = 0; j < 4; j++)
            #pragma unroll
            for (int r = 0; r < 4; r++) acc[i][j][r] = 0.f;

    // per-thread cp.async source/dest (4 x 16B for A, 4 for B, per stage)
    int nk = K / KC;

    // stage load: stage s, chunk c
    auto load_stage = [&](int s, int c) {
        uint32_t sA = sbase + (uint32_t)(s * STG_FLOATS) * 4u;
        uint32_t sB = sA + 128u * PITCH * 4u;
        const float* ag = A + (size_t)brow * K + c * KC;
        const float* bg = Bt + (size_t)bcol * K + c * KC;
        #pragma unroll
        for (int i = 0; i < 4; i++) {
            int idx = t + i * 256;             // 0..1023
            int r = idx >> 3, cg = idx & 7;
            cp_async16(sA + (uint32_t)(r * PITCH + cg * 4) * 4u,
                       ag + (size_t)r * K + cg * 4);
            cp_async16(sB + (uint32_t)(r * PITCH + cg * 4) * 4u,
                       bg + (size_t)r * K + cg * 4);
        }
        cp_commit();
    };

    load_stage(0, 0);

    for (int c = 0; c < nk; c++) {
        if (c + 1 < nk) load_stage((c + 1) & 1, c + 1);
        if (c + 1 < nk) cp_wait1(); else cp_wait0();
        __syncthreads();

        const float* As = sm + (c & 1) * STG_FLOATS;
        const float* Bs = As + 128 * PITCH;

        #pragma unroll
        for (int ks = 0; ks < 4; ks++) {
            int k0 = ks * 8;
            uint32_t af[4][4], bf[4][2];
            #pragma unroll
            for (int mt = 0; mt < 4; mt++) {
                int r0 = wm * 64 + mt * 16 + g;
                af[mt][0] = __float_as_uint(As[r0 * PITCH + k0 + tg]);
                af[mt][1] = __float_as_uint(As[(r0 + 8) * PITCH + k0 + tg]);
                af[mt][2] = __float_as_uint(As[r0 * PITCH + k0 + tg + 4]);
                af[mt][3] = __float_as_uint(As[(r0 + 8) * PITCH + k0 + tg + 4]);
            }
            #pragma unroll
            for (int nt = 0; nt < 4; nt++) {
                int n0 = wn * 32 + nt * 8 + g;
                bf[nt][0] = __float_as_uint(Bs[n0 * PITCH + k0 + tg]);
                bf[nt][1] = __float_as_uint(Bs[n0 * PITCH + k0 + tg + 4]);
            }
            #pragma unroll
            for (int mt = 0; mt < 4; mt++)
                #pragma unroll
                for (int nt = 0; nt < 4; nt++)
                    mma_tf32(acc[mt][nt], af[mt], bf[nt]);
        }
        __syncthreads();
    }

    // epilogue: c0:(g,2t) c1:(g,2t+1) c2:(g+8,2t) c3:(g+8,2t+1)
    #pragma unroll
    for (int mt = 0; mt < 4; mt++) {
        int r0 = brow + wm * 64 + mt * 16 + g;
        #pragma unroll
        for (int nt = 0; nt < 4; nt++) {
            int col = bcol + wn * 32 + nt * 8 + tg * 2;
            float2 bv2 = *(const float2*)(bias + col);
            float v0 = acc[mt][nt][0] + bv2.x;
            float v1 = acc[mt][nt][1] + bv2.y;
            float v2 = acc[mt][nt][2] + bv2.x;
            float v3 = acc[mt][nt][3] + bv2.y;
            if (RELU) {
                v0 = fmaxf(v0, 0.f); v1 = fmaxf(v1, 0.f);
                v2 = fmaxf(v2, 0.f); v3 = fmaxf(v3, 0.f);
            }
            if (CVT) {
                v0 = cvt_tf32f(v0); v1 = cvt_tf32f(v1);
                v2 = cvt_tf32f(v2); v3 = cvt_tf32f(v3);
            }
            *(float2*)(C + (size_t)r0 * N + col)       = make_float2(v0, v1);
            *(float2*)(C + (size_t)(r0 + 8) * N + col) = make_float2(v2, v3);
        }
    }
}

// ---------------- LayerNorm (optional fused residual add, optional tf32 round) --
template<bool CVT>
__global__ __launch_bounds__(256) void ln_kernel(
    const float* __restrict__ in1, const float* __restrict__ in2,
    const float* __restrict__ gam, const float* __restrict__ bet,
    float* __restrict__ out)
{
    int row = blockIdx.x;
    int t = threadIdx.x;
    const float* p1 = in1 + (size_t)row * DD;
    float v0 = p1[t];
    float v1 = p1[t + 256];
    if (in2) {
        const float* p2 = in2 + (size_t)row * DD;
        v0 += p2[t];
        v1 += p2[t + 256];
    }
    __shared__ float red[8];
    float s = v0 + v1;
    #pragma unroll
    for (int o = 16; o > 0; o >>= 1) s += __shfl_xor_sync(0xffffffffu, s, o);
    if ((t & 31) == 0) red[t >> 5] = s;
    __syncthreads();
    float tot = 0.f;
    #pragma unroll
    for (int i = 0; i < 8; i++) tot += red[i];
    float mu = tot * (1.0f / DD);
    float d0 = v0 - mu, d1 = v1 - mu;
    s = d0 * d0 + d1 * d1;
    #pragma unroll
    for (int o = 16; o > 0; o >>= 1) s += __shfl_xor_sync(0xffffffffu, s, o);
    __syncthreads();
    if ((t & 31) == 0) red[t >> 5] = s;
    __syncthreads();
    tot = 0.f;
    #pragma unroll
    for (int i = 0; i < 8; i++) tot += red[i];
    float r = rsqrtf(tot * (1.0f / DD) + 1e-3f);
    float o0 = d0 * r * gam[t]       + bet[t];
    float o1 = d1 * r * gam[t + 256] + bet[t + 256];
    if (CVT) { o0 = cvt_tf32f(o0); o1 = cvt_tf32f(o1); }
    out[(size_t)row * DD + t]       = o0;
    out[(size_t)row * DD + t + 256] = o1;
}

// ---------------- Flash attention (fp32, online softmax) ----------------
// q/k/v packed in g_qkv with row stride NQKV=1536 (q:+0, k:+512, v:+1024)
#define APITCH 65
#define ATTN_SMEM (4 * 64 * APITCH * (int)sizeof(float))

__global__ __launch_bounds__(256) void attn_kernel(
    const float* __restrict__ QKV, const float* __restrict__ mask,
    float* __restrict__ O)
{
    extern __shared__ float smf[];
    float* Qs = smf;
    float* Ks = Qs + 64 * APITCH;
    float* Vs = Ks + 64 * APITCH;
    float* Ps = Vs + 64 * APITCH;

    int b = blockIdx.z, h = blockIdx.y, qt = blockIdx.x;
    int t = threadIdx.x;
    int ty = t >> 4, tx = t & 15;

    const float* qptr  = QKV + ((size_t)(b * TT) + qt * 64) * NQKV + h * 64;
    const float* kptr0 = QKV + (size_t)(b * TT) * NQKV + h * 64 + 512;
    const float* vptr0 = QKV + (size_t)(b * TT) * NQKV + h * 64 + 1024;
    const float* mptr  = mask + ((size_t)b * TT + qt * 64) * TT;

    #pragma unroll
    for (int i = 0; i < 4; i++) {
        int idx = t + i * 256;
        int r = idx >> 4, c = idx & 15;
        float4 v = *(const float4*)(qptr + (size_t)r * NQKV + c * 4);
        float* dst = Qs + r * APITCH + c * 4;
        dst[0] = v.x; dst[1] = v.y; dst[2] = v.z; dst[3] = v.w;
    }

    float m[4], l[4], acc[4][4];
    #pragma unroll
    for (int i = 0; i < 4; i++) {
        m[i] = -1e30f; l[i] = 0.f;
        #pragma unroll
        for (int j = 0; j < 4; j++) acc[i][j] = 0.f;
    }
    __syncthreads();

    for (int kt = 0; kt < TT / 64; kt++) {
        #pragma unroll
        for (int i = 0; i < 4; i++) {
            int idx = t + i * 256;
            int r = idx >> 4, c = idx & 15;
            float4 kv = *(const float4*)(kptr0 + (size_t)(kt * 64 + r) * NQKV + c * 4);
            float* kd = Ks + r * APITCH + c * 4;
            kd[0] = kv.x; kd[1] = kv.y; kd[2] = kv.z; kd[3] = kv.w;
            float4 vv = *(const float4*)(vptr0 + (size_t)(kt * 64 + r) * NQKV + c * 4);
            float* vd = Vs + r * APITCH + c * 4;
            vd[0] = vv.x; vd[1] = vv.y; vd[2] = vv.z; vd[3] = vv.w;
        }
        __syncthreads();

        float s[4][4];
        #pragma unroll
        for (int i = 0; i < 4; i++)
            #pragma unroll
            for (int j = 0; j < 4; j++) s[i][j] = 0.f;
        #pragma unroll 8
        for (int d = 0; d < 64; d++) {
            float qv[4], kv[4];
            #pragma unroll
            for (int i = 0; i < 4; i++) qv[i] = Qs[(ty*4 + i) * APITCH + d];
            #pragma unroll
            for (int j = 0; j < 4; j++) kv[j] = Ks[(tx + 16*j) * APITCH + d];
            #pragma unroll
            for (int i = 0; i < 4; i++)
                #pragma unroll
                for (int j = 0; j < 4; j++)
                    s[i][j] += qv[i] * kv[j];
        }

        #pragma unroll
        for (int i = 0; i < 4; i++) {
            int qrow = ty*4 + i;
            float rm = -1e30f;
            #pragma unroll
            for (int j = 0; j < 4; j++) {
                float mk = mptr[(size_t)qrow * TT + kt * 64 + tx + 16*j];
                float sv = s[i][j] * 0.125f + (mk - 1.0f) * 1e9f;
                s[i][j] = sv;
                rm = fmaxf(rm, sv);
            }
            #pragma unroll
            for (int o = 8; o > 0; o >>= 1)
                rm = fmaxf(rm, __shfl_xor_sync(0xffffffffu, rm, o));
            float mn = fmaxf(m[i], rm);
            float corr = __expf(m[i] - mn);
            float rl = 0.f;
            #pragma unroll
            for (int j = 0; j < 4; j++) {
                float p = __expf(s[i][j] - mn);
                s[i][j] = p;
                rl += p;
            }
            #pragma unroll
            for (int o = 8; o > 0; o >>= 1)
                rl += __shfl_xor_sync(0xffffffffu, rl, o);
            l[i] = l[i] * corr + rl;
            m[i] = mn;
            #pragma unroll
            for (int j = 0; j < 4; j++) acc[i][j] *= corr;
            #pragma unroll
            for (int j = 0; j < 4; j++) Ps[qrow * APITCH + tx + 16*j] = s[i][j];
        }
        __syncthreads();

        #pragma unroll 8
        for (int col = 0; col < 64; col++) {
            float pv[4], vv[4];
            #pragma unroll
            for (int i = 0; i < 4; i++) pv[i] = Ps[(ty*4 + i) * APITCH + col];
            #pragma unroll
            for (int j = 0; j < 4; j++) vv[j] = Vs[col * APITCH + tx + 16*j];
            #pragma unroll
            for (int i = 0; i < 4; i++)
                #pragma unroll
                for (int j = 0; j < 4; j++)
                    acc[i][j] += pv[i] * vv[j];
        }
        __syncthreads();
    }

    float* optr = O + ((size_t)(b * TT) + qt * 64) * DD + h * 64;
    #pragma unroll
    for (int i = 0; i < 4; i++) {
        float inv = 1.0f / l[i];
        #pragma unroll
        for (int j = 0; j < 4; j++)
            optr[(size_t)(ty*4 + i) * DD + tx + 16*j] = acc[i][j] * inv;
    }
}

// ---------------- launch ----------------
extern "C" void kernel_launch(void* const* d_in, const int* in_sizes, int n_in,
                              void* d_out, int out_size)
{
    const float* x       = (const float*)d_in[0];
    const float* mask    = (const float*)d_in[1];
    const float* ln_in_g = (const float*)d_in[2];
    const float* ln_in_b = (const float*)d_in[3];
    const float* Wq = (const float*)d_in[4];
    const float* bq = (const float*)d_in[5];
    const float* Wk = (const float*)d_in[6];
    const float* bk = (const float*)d_in[7];
    const float* Wv = (const float*)d_in[8];
    const float* bv = (const float*)d_in[9];
    const float* ln1_g = (const float*)d_in[10];
    const float* ln1_b = (const float*)d_in[11];
    const float* W1 = (const float*)d_in[12];
    const float* b1 = (const float*)d_in[13];
    const float* W2 = (const float*)d_in[14];
    const float* b2 = (const float*)d_in[15];
    const float* ln2_g = (const float*)d_in[16];
    const float* ln2_b = (const float*)d_in[17];
    float* out = (float*)d_out;

    float *hbuf, *qkvbuf, *attnbuf, *abuf, *f1buf, *f2buf;
    float *wqkvt, *w1t, *w2t, *bqkv;
    cudaGetSymbolAddress((void**)&hbuf,    g_h);
    cudaGetSymbolAddress((void**)&qkvbuf,  g_qkv);
    cudaGetSymbolAddress((void**)&attnbuf, g_attn);
    cudaGetSymbolAddress((void**)&abuf,    g_a);
    cudaGetSymbolAddress((void**)&f1buf,   g_f1);
    cudaGetSymbolAddress((void**)&f2buf,   g_f2);
    cudaGetSymbolAddress((void**)&wqkvt,   g_Wqkvt);
    cudaGetSymbolAddress((void**)&w1t,     g_W1t);
    cudaGetSymbolAddress((void**)&w2t,     g_W2t);
    cudaGetSymbolAddress((void**)&bqkv,    g_bqkv);

    cudaFuncSetAttribute(attn_kernel,
                         cudaFuncAttributeMaxDynamicSharedMemorySize, ATTN_SMEM);
    cudaFuncSetAttribute(tc_gemm<false, false>,
                         cudaFuncAttributeMaxDynamicSharedMemorySize, GEMM_SMEM);
    cudaFuncSetAttribute(tc_gemm<true, true>,
                         cudaFuncAttributeMaxDynamicSharedMemorySize, GEMM_SMEM);

    dim3 tb(32, 8);
    // weight transposes (+tf32 rna convert): W[R,N] -> Wt[N,R]
    transpose_tf32<<<dim3(DD/32, DD/32), tb>>>(Wq, wqkvt,           DD, DD);
    transpose_tf32<<<dim3(DD/32, DD/32), tb>>>(Wk, wqkvt + DD*DD,   DD, DD);
    transpose_tf32<<<dim3(DD/32, DD/32), tb>>>(Wv, wqkvt + 2*DD*DD, DD, DD);
    transpose_tf32<<<dim3(FF/32, DD/32), tb>>>(W1, w1t, DD, FF);
    transpose_tf32<<<dim3(DD/32, FF/32), tb>>>(W2, w2t, FF, DD);
    concat_bias<<<NQKV/256, 256>>>(bq, bk, bv, bqkv);

    // 1. h = LN(x)  (tf32-rounded: feeds QKV GEMM)
    ln_kernel<true><<<MM, 256>>>(x, nullptr, ln_in_g, ln_in_b, hbuf);

    // 2. fused QKV: [M,1536] = h @ [Wq|Wk|Wv]
    tc_gemm<false, false><<<dim3(NQKV/128, MM/128), 256, GEMM_SMEM>>>(
        hbuf, wqkvt, bqkv, qkvbuf, MM, NQKV, DD);

    // 3. masked flash attention
    attn_kernel<<<dim3(TT/64, HH, BB), 256, ATTN_SMEM>>>(qkvbuf, mask, attnbuf);

    // 4. a = LN1(attn + x)  (tf32-rounded: feeds FFN1)
    ln_kernel<true><<<MM, 256>>>(attnbuf, x, ln1_g, ln1_b, abuf);

    // 5. FFN (f1 relu-ed AND tf32-rounded: feeds FFN2)
    tc_gemm<true, true><<<dim3(FF/128, MM/128), 256, GEMM_SMEM>>>(
        abuf, w1t, b1, f1buf, MM, FF, DD);
    tc_gemm<false, false><<<dim3(DD/128, MM/128), 256, GEMM_SMEM>>>(
        f1buf, w2t, b2, f2buf, MM, DD, FF);

    // 6. out = LN2(f + a)
    ln_kernel<false><<<MM, 256>>>(f2buf, abuf, ln2_g, ln2_b, out);
}

// round 9
// speedup vs baseline: 2.6944x; 1.4842x over previous
#include <cuda_runtime.h>
#include <cstdint>
#include <math.h>

#define BB 8
#define TT 1024
#define DD 512
#define HH 8
#define FF 2048
#define MM (BB*TT)   // 8192 rows
#define NQKV (3*DD)  // 1536

// ---------------- scratch (allocation-free: __device__ globals) ----------------
__device__ float g_h[MM*DD];        // LN(x), tf32-rounded
__device__ float g_qkv[MM*NQKV];    // fused QKV output [M,1536]
__device__ float g_attn[MM*DD];     // attention output (pre-residual)
__device__ float g_a[MM*DD];        // LN1(attn + x), tf32-rounded
__device__ float g_f1[MM*FF];       // relu(a@W1+b1), tf32-rounded
__device__ float g_f2[MM*DD];       // f1@W2+b2
__device__ float g_Wqkvt[NQKV*DD];  // [1536,512] tf32 (rows: q|k|v), transposed
__device__ float g_W1t[FF*DD];      // [2048,512] tf32
__device__ float g_W2t[DD*FF];      // [512,2048] tf32
__device__ float g_bqkv[NQKV];

// ---------------- helpers ----------------
__device__ __forceinline__ uint32_t s2u(const void* p) {
    uint32_t a;
    asm("{ .reg .u64 t; cvta.to.shared.u64 t, %1; cvt.u32.u64 %0, t; }" : "=r"(a) : "l"(p));
    return a;
}
__device__ __forceinline__ float cvt_tf32f(float x) {
    uint32_t r; asm("cvt.rna.tf32.f32 %0, %1;" : "=r"(r) : "f"(x));
    return __uint_as_float(r);
}
__device__ __forceinline__ void cp_async16(uint32_t saddr, const void* gaddr) {
    asm volatile("cp.async.ca.shared.global [%0], [%1], 16;" :: "r"(saddr), "l"(gaddr));
}
__device__ __forceinline__ void cp_commit() {
    asm volatile("cp.async.commit_group;" ::: "memory");
}
__device__ __forceinline__ void cp_wait1() {
    asm volatile("cp.async.wait_group 1;" ::: "memory");
}
__device__ __forceinline__ void cp_wait0() {
    asm volatile("cp.async.wait_group 0;" ::: "memory");
}
// D = A(row,m16k8 tf32) * B(col,k8n8 tf32) + D, fp32 accum
__device__ __forceinline__ void mma_tf32(float* c, const uint32_t* a, const uint32_t* b) {
    asm volatile(
        "mma.sync.aligned.m16n8k8.row.col.f32.tf32.tf32.f32 "
        "{%0,%1,%2,%3}, {%4,%5,%6,%7}, {%8,%9}, {%0,%1,%2,%3};"
        : "+f"(c[0]), "+f"(c[1]), "+f"(c[2]), "+f"(c[3])
        : "r"(a[0]), "r"(a[1]), "r"(a[2]), "r"(a[3]), "r"(b[0]), "r"(b[1]));
}

// ---------------- weight transpose + tf32(rna) convert: W[R,N] -> Wt[N,R] -------
__global__ void transpose_tf32(const float* __restrict__ W, float* __restrict__ Wt,
                               int R, int N) {
    __shared__ float tile[32][33];
    int rb = blockIdx.y * 32, nb = blockIdx.x * 32;
    int tx = threadIdx.x, ty = threadIdx.y;   // 32 x 8
    #pragma unroll
    for (int i = 0; i < 32; i += 8)
        tile[ty + i][tx] = W[(size_t)(rb + ty + i) * N + nb + tx];
    __syncthreads();
    #pragma unroll
    for (int i = 0; i < 32; i += 8)
        Wt[(size_t)(nb + ty + i) * R + rb + tx] = cvt_tf32f(tile[tx][ty + i]);
}

__global__ void concat_bias(const float* __restrict__ bq, const float* __restrict__ bk,
                            const float* __restrict__ bv, float* __restrict__ o) {
    int t = blockIdx.x * 256 + threadIdx.x;
    if (t < NQKV)
        o[t] = t < 512 ? bq[t] : (t < 1024 ? bk[t - 512] : bv[t - 1024]);
}

// ---------------- tf32 mma.sync GEMM: C[M,N] = A[M,K] @ Bt[N,K]^T + bias --------
#define KC 32
#define PITCH 36
#define STG_FLOATS (2 * 128 * PITCH)
#define GEMM_SMEM (2 * STG_FLOATS * (int)sizeof(float))   // 73728 B

template<bool RELU, bool CVT>
__global__ __launch_bounds__(256)
void tc_gemm(const float* __restrict__ A, const float* __restrict__ Bt,
             const float* __restrict__ bias, float* __restrict__ C,
             int M, int N, int K)
{
    extern __shared__ float sm[];
    uint32_t sbase = s2u(sm);

    int t = threadIdx.x;
    int wid = t >> 5, lane = t & 31;
    int g = lane >> 2, tg = lane & 3;
    int wm = wid & 1, wn = wid >> 1;
    int brow = blockIdx.y * 128, bcol = blockIdx.x * 128;

    float acc[4][4][4];
    #pragma unroll
    for (int i = 0; i < 4; i++)
        #pragma unroll
        for (int j = 0; j < 4; j++)
            #pragma unroll
            for (int r = 0; r < 4; r++) acc[i][j][r] = 0.f;

    int nk = K / KC;

    auto load_stage = [&](int s, int c) {
        uint32_t sA = sbase + (uint32_t)(s * STG_FLOATS) * 4u;
        uint32_t sB = sA + 128u * PITCH * 4u;
        const float* ag = A + (size_t)brow * K + c * KC;
        const float* bg = Bt + (size_t)bcol * K + c * KC;
        #pragma unroll
        for (int i = 0; i < 4; i++) {
            int idx = t + i * 256;
            int r = idx >> 3, cg = idx & 7;
            cp_async16(sA + (uint32_t)(r * PITCH + cg * 4) * 4u,
                       ag + (size_t)r * K + cg * 4);
            cp_async16(sB + (uint32_t)(r * PITCH + cg * 4) * 4u,
                       bg + (size_t)r * K + cg * 4);
        }
        cp_commit();
    };

    load_stage(0, 0);

    for (int c = 0; c < nk; c++) {
        if (c + 1 < nk) load_stage((c + 1) & 1, c + 1);
        if (c + 1 < nk) cp_wait1(); else cp_wait0();
        __syncthreads();

        const float* As = sm + (c & 1) * STG_FLOATS;
        const float* Bs = As + 128 * PITCH;

        #pragma unroll
        for (int ks = 0; ks < 4; ks++) {
            int k0 = ks * 8;
            uint32_t af[4][4], bf[4][2];
            #pragma unroll
            for (int mt = 0; mt < 4; mt++) {
                int r0 = wm * 64 + mt * 16 + g;
                af[mt][0] = __float_as_uint(As[r0 * PITCH + k0 + tg]);
                af[mt][1] = __float_as_uint(As[(r0 + 8) * PITCH + k0 + tg]);
                af[mt][2] = __float_as_uint(As[r0 * PITCH + k0 + tg + 4]);
                af[mt][3] = __float_as_uint(As[(r0 + 8) * PITCH + k0 + tg + 4]);
            }
            #pragma unroll
            for (int nt = 0; nt < 4; nt++) {
                int n0 = wn * 32 + nt * 8 + g;
                bf[nt][0] = __float_as_uint(Bs[n0 * PITCH + k0 + tg]);
                bf[nt][1] = __float_as_uint(Bs[n0 * PITCH + k0 + tg + 4]);
            }
            #pragma unroll
            for (int mt = 0; mt < 4; mt++)
                #pragma unroll
                for (int nt = 0; nt < 4; nt++)
                    mma_tf32(acc[mt][nt], af[mt], bf[nt]);
        }
        __syncthreads();
    }

    #pragma unroll
    for (int mt = 0; mt < 4; mt++) {
        int r0 = brow + wm * 64 + mt * 16 + g;
        #pragma unroll
        for (int nt = 0; nt < 4; nt++) {
            int col = bcol + wn * 32 + nt * 8 + tg * 2;
            float2 bv2 = *(const float2*)(bias + col);
            float v0 = acc[mt][nt][0] + bv2.x;
            float v1 = acc[mt][nt][1] + bv2.y;
            float v2 = acc[mt][nt][2] + bv2.x;
            float v3 = acc[mt][nt][3] + bv2.y;
            if (RELU) {
                v0 = fmaxf(v0, 0.f); v1 = fmaxf(v1, 0.f);
                v2 = fmaxf(v2, 0.f); v3 = fmaxf(v3, 0.f);
            }
            if (CVT) {
                v0 = cvt_tf32f(v0); v1 = cvt_tf32f(v1);
                v2 = cvt_tf32f(v2); v3 = cvt_tf32f(v3);
            }
            *(float2*)(C + (size_t)r0 * N + col)       = make_float2(v0, v1);
            *(float2*)(C + (size_t)(r0 + 8) * N + col) = make_float2(v2, v3);
        }
    }
}

// ---------------- LayerNorm (optional fused residual add, optional tf32 round) --
template<bool CVT>
__global__ __launch_bounds__(256) void ln_kernel(
    const float* __restrict__ in1, const float* __restrict__ in2,
    const float* __restrict__ gam, const float* __restrict__ bet,
    float* __restrict__ out)
{
    int row = blockIdx.x;
    int t = threadIdx.x;
    const float* p1 = in1 + (size_t)row * DD;
    float v0 = p1[t];
    float v1 = p1[t + 256];
    if (in2) {
        const float* p2 = in2 + (size_t)row * DD;
        v0 += p2[t];
        v1 += p2[t + 256];
    }
    __shared__ float red[8];
    float s = v0 + v1;
    #pragma unroll
    for (int o = 16; o > 0; o >>= 1) s += __shfl_xor_sync(0xffffffffu, s, o);
    if ((t & 31) == 0) red[t >> 5] = s;
    __syncthreads();
    float tot = 0.f;
    #pragma unroll
    for (int i = 0; i < 8; i++) tot += red[i];
    float mu = tot * (1.0f / DD);
    float d0 = v0 - mu, d1 = v1 - mu;
    s = d0 * d0 + d1 * d1;
    #pragma unroll
    for (int o = 16; o > 0; o >>= 1) s += __shfl_xor_sync(0xffffffffu, s, o);
    __syncthreads();
    if ((t & 31) == 0) red[t >> 5] = s;
    __syncthreads();
    tot = 0.f;
    #pragma unroll
    for (int i = 0; i < 8; i++) tot += red[i];
    float r = rsqrtf(tot * (1.0f / DD) + 1e-3f);
    float o0 = d0 * r * gam[t]       + bet[t];
    float o1 = d1 * r * gam[t + 256] + bet[t + 256];
    if (CVT) { o0 = cvt_tf32f(o0); o1 = cvt_tf32f(o1); }
    out[(size_t)row * DD + t]       = o0;
    out[(size_t)row * DD + t + 256] = o1;
}

// ---------------- tensor-core flash attention (tf32 mma, online softmax) --------
// CTA: 128 queries x 64 keys, DK=64, 256 threads (8 warps; warp w = query rows w*16).
// SMEM pitch 68 floats: fragment reads land on 32 distinct banks (68 mod 32 = 4).
#define QTILE 128
#define KTILE 64
#define AP 68
#define ATTN_SMEM ((QTILE + KTILE + KTILE + QTILE) * AP * (int)sizeof(float))  // 104448

__global__ __launch_bounds__(256) void attn_tc(
    const float* __restrict__ QKV, const float* __restrict__ mask,
    float* __restrict__ O)
{
    extern __shared__ float smf[];
    float* Qs = smf;                    // [128][68] tf32 (rows q, cols d)
    float* Ks = Qs + QTILE * AP;        // [64][68]  (rows k, cols d)
    float* Vt = Ks + KTILE * AP;        // [64][68]  (rows d, cols s) -- transposed
    float* Ps = Vt + KTILE * AP;        // [128][68] (rows q, cols s)

    int b = blockIdx.z, h = blockIdx.y, qt = blockIdx.x;
    int t = threadIdx.x;
    int w = t >> 5, lane = t & 31;
    int g = lane >> 2, tg = lane & 3;

    const float* qptr  = QKV + ((size_t)(b * TT) + qt * QTILE) * NQKV + h * 64;
    const float* kptr0 = QKV + (size_t)(b * TT) * NQKV + h * 64 + 512;
    const float* vptr0 = QKV + (size_t)(b * TT) * NQKV + h * 64 + 1024;

    // load Q tile (tf32-rounded)
    #pragma unroll
    for (int i = 0; i < 8; i++) {
        int idx = t + i * 256;              // 2048 float4 slots
        int r = idx >> 4, c = idx & 15;
        float4 v = *(const float4*)(qptr + (size_t)r * NQKV + c * 4);
        float4 w4 = make_float4(cvt_tf32f(v.x), cvt_tf32f(v.y),
                                cvt_tf32f(v.z), cvt_tf32f(v.w));
        *(float4*)&Qs[r * AP + c * 4] = w4;
    }

    float m0 = -1e30f, m1 = -1e30f, l0 = 0.f, l1 = 0.f;
    float oacc[8][4];
    #pragma unroll
    for (int dt = 0; dt < 8; dt++)
        #pragma unroll
        for (int r = 0; r < 4; r++) oacc[dt][r] = 0.f;

    const float* mrow0 = mask + ((size_t)b * TT + qt * QTILE + w * 16 + g) * TT;
    const float* mrow1 = mrow0 + 8 * TT;

    for (int kt = 0; kt < TT / KTILE; kt++) {
        // ---- load K (rows k, cols d) and V transposed (rows d, cols s) ----
        #pragma unroll
        for (int i = 0; i < 4; i++) {
            int idx = t + i * 256;          // 1024 float4 slots
            int r = idx >> 4, c = idx & 15;
            float4 v = *(const float4*)(kptr0 + (size_t)(kt * KTILE + r) * NQKV + c * 4);
            float4 w4 = make_float4(cvt_tf32f(v.x), cvt_tf32f(v.y),
                                    cvt_tf32f(v.z), cvt_tf32f(v.w));
            *(float4*)&Ks[r * AP + c * 4] = w4;
        }
        #pragma unroll
        for (int i = 0; i < 4; i++) {
            int idx = t + i * 256;          // 64 d x 16 s-groups
            int d = idx & 63, s0 = (idx >> 6) * 4;
            const float* vp = vptr0 + (size_t)(kt * KTILE + s0) * NQKV + d;
            float4 w4 = make_float4(cvt_tf32f(vp[0]),
                                    cvt_tf32f(vp[NQKV]),
                                    cvt_tf32f(vp[2 * NQKV]),
                                    cvt_tf32f(vp[3 * NQKV]));
            *(float4*)&Vt[d * AP + s0] = w4;
        }
        __syncthreads();

        // ---- S = Q K^T ----
        float sacc[8][4];
        #pragma unroll
        for (int nt = 0; nt < 8; nt++)
            #pragma unroll
            for (int r = 0; r < 4; r++) sacc[nt][r] = 0.f;

        #pragma unroll
        for (int kc = 0; kc < 8; kc++) {
            int k0 = kc * 8;
            int r0 = w * 16 + g;
            uint32_t af[4];
            af[0] = __float_as_uint(Qs[r0 * AP + k0 + tg]);
            af[1] = __float_as_uint(Qs[(r0 + 8) * AP + k0 + tg]);
            af[2] = __float_as_uint(Qs[r0 * AP + k0 + tg + 4]);
            af[3] = __float_as_uint(Qs[(r0 + 8) * AP + k0 + tg + 4]);
            #pragma unroll
            for (int nt = 0; nt < 8; nt++) {
                uint32_t bf[2];
                bf[0] = __float_as_uint(Ks[(nt * 8 + g) * AP + k0 + tg]);
                bf[1] = __float_as_uint(Ks[(nt * 8 + g) * AP + k0 + tg + 4]);
                mma_tf32(sacc[nt], af, bf);
            }
        }

        // ---- scale + mask + online softmax on fragments ----
        const float* mk0 = mrow0 + kt * KTILE;
        const float* mk1 = mrow1 + kt * KTILE;
        float rm0 = -1e30f, rm1 = -1e30f;
        #pragma unroll
        for (int nt = 0; nt < 8; nt++) {
            float2 a0 = *(const float2*)(mk0 + nt * 8 + 2 * tg);
            float2 a1 = *(const float2*)(mk1 + nt * 8 + 2 * tg);
            sacc[nt][0] = sacc[nt][0] * 0.125f + (a0.x - 1.f) * 1e9f;
            sacc[nt][1] = sacc[nt][1] * 0.125f + (a0.y - 1.f) * 1e9f;
            sacc[nt][2] = sacc[nt][2] * 0.125f + (a1.x - 1.f) * 1e9f;
            sacc[nt][3] = sacc[nt][3] * 0.125f + (a1.y - 1.f) * 1e9f;
            rm0 = fmaxf(rm0, fmaxf(sacc[nt][0], sacc[nt][1]));
            rm1 = fmaxf(rm1, fmaxf(sacc[nt][2], sacc[nt][3]));
        }
        rm0 = fmaxf(rm0, __shfl_xor_sync(0xffffffffu, rm0, 1));
        rm0 = fmaxf(rm0, __shfl_xor_sync(0xffffffffu, rm0, 2));
        rm1 = fmaxf(rm1, __shfl_xor_sync(0xffffffffu, rm1, 1));
        rm1 = fmaxf(rm1, __shfl_xor_sync(0xffffffffu, rm1, 2));

        float mn0 = fmaxf(m0, rm0), mn1 = fmaxf(m1, rm1);
        float corr0 = __expf(m0 - mn0), corr1 = __expf(m1 - mn1);
        m0 = mn0; m1 = mn1;

        float rl0 = 0.f, rl1 = 0.f;
        int q0 = w * 16 + g;
        #pragma unroll
        for (int nt = 0; nt < 8; nt++) {
            float p0 = __expf(sacc[nt][0] - mn0);
            float p1 = __expf(sacc[nt][1] - mn0);
            float p2 = __expf(sacc[nt][2] - mn1);
            float p3 = __expf(sacc[nt][3] - mn1);
            rl0 += p0 + p1;
            rl1 += p2 + p3;
            *(float2*)&Ps[q0 * AP + nt * 8 + 2 * tg] =
                make_float2(cvt_tf32f(p0), cvt_tf32f(p1));
            *(float2*)&Ps[(q0 + 8) * AP + nt * 8 + 2 * tg] =
                make_float2(cvt_tf32f(p2), cvt_tf32f(p3));
        }
        rl0 += __shfl_xor_sync(0xffffffffu, rl0, 1);
        rl0 += __shfl_xor_sync(0xffffffffu, rl0, 2);
        rl1 += __shfl_xor_sync(0xffffffffu, rl1, 1);
        rl1 += __shfl_xor_sync(0xffffffffu, rl1, 2);
        l0 = l0 * corr0 + rl0;
        l1 = l1 * corr1 + rl1;

        #pragma unroll
        for (int dt = 0; dt < 8; dt++) {
            oacc[dt][0] *= corr0; oacc[dt][1] *= corr0;
            oacc[dt][2] *= corr1; oacc[dt][3] *= corr1;
        }
        __syncwarp();

        // ---- O += P @ V  (A = Ps rows, B = Vt[d][s]) ----
        #pragma unroll
        for (int kc = 0; kc < 8; kc++) {
            int k0 = kc * 8;
            uint32_t af[4];
            af[0] = __float_as_uint(Ps[q0 * AP + k0 + tg]);
            af[1] = __float_as_uint(Ps[(q0 + 8) * AP + k0 + tg]);
            af[2] = __float_as_uint(Ps[q0 * AP + k0 + tg + 4]);
            af[3] = __float_as_uint(Ps[(q0 + 8) * AP + k0 + tg + 4]);
            #pragma unroll
            for (int dt = 0; dt < 8; dt++) {
                uint32_t bf[2];
                bf[0] = __float_as_uint(Vt[(dt * 8 + g) * AP + k0 + tg]);
                bf[1] = __float_as_uint(Vt[(dt * 8 + g) * AP + k0 + tg + 4]);
                mma_tf32(oacc[dt], af, bf);
            }
        }
        __syncthreads();
    }

    // ---- epilogue: divide by l, write out ----
    float inv0 = 1.0f / l0, inv1 = 1.0f / l1;
    float* optr = O + ((size_t)(b * TT) + qt * QTILE + w * 16 + g) * DD + h * 64;
    #pragma unroll
    for (int dt = 0; dt < 8; dt++) {
        int col = dt * 8 + 2 * tg;
        *(float2*)(optr + col) =
            make_float2(oacc[dt][0] * inv0, oacc[dt][1] * inv0);
        *(float2*)(optr + 8 * DD + col) =
            make_float2(oacc[dt][2] * inv1, oacc[dt][3] * inv1);
    }
}

// ---------------- launch ----------------
extern "C" void kernel_launch(void* const* d_in, const int* in_sizes, int n_in,
                              void* d_out, int out_size)
{
    const float* x       = (const float*)d_in[0];
    const float* mask    = (const float*)d_in[1];
    const float* ln_in_g = (const float*)d_in[2];
    const float* ln_in_b = (const float*)d_in[3];
    const float* Wq = (const float*)d_in[4];
    const float* bq = (const float*)d_in[5];
    const float* Wk = (const float*)d_in[6];
    const float* bk = (const float*)d_in[7];
    const float* Wv = (const float*)d_in[8];
    const float* bv = (const float*)d_in[9];
    const float* ln1_g = (const float*)d_in[10];
    const float* ln1_b = (const float*)d_in[11];
    const float* W1 = (const float*)d_in[12];
    const float* b1 = (const float*)d_in[13];
    const float* W2 = (const float*)d_in[14];
    const float* b2 = (const float*)d_in[15];
    const float* ln2_g = (const float*)d_in[16];
    const float* ln2_b = (const float*)d_in[17];
    float* out = (float*)d_out;

    float *hbuf, *qkvbuf, *attnbuf, *abuf, *f1buf, *f2buf;
    float *wqkvt, *w1t, *w2t, *bqkv;
    cudaGetSymbolAddress((void**)&hbuf,    g_h);
    cudaGetSymbolAddress((void**)&qkvbuf,  g_qkv);
    cudaGetSymbolAddress((void**)&attnbuf, g_attn);
    cudaGetSymbolAddress((void**)&abuf,    g_a);
    cudaGetSymbolAddress((void**)&f1buf,   g_f1);
    cudaGetSymbolAddress((void**)&f2buf,   g_f2);
    cudaGetSymbolAddress((void**)&wqkvt,   g_Wqkvt);
    cudaGetSymbolAddress((void**)&w1t,     g_W1t);
    cudaGetSymbolAddress((void**)&w2t,     g_W2t);
    cudaGetSymbolAddress((void**)&bqkv,    g_bqkv);

    cudaFuncSetAttribute(attn_tc,
                         cudaFuncAttributeMaxDynamicSharedMemorySize, ATTN_SMEM);
    cudaFuncSetAttribute(tc_gemm<false, false>,
                         cudaFuncAttributeMaxDynamicSharedMemorySize, GEMM_SMEM);
    cudaFuncSetAttribute(tc_gemm<true, true>,
                         cudaFuncAttributeMaxDynamicSharedMemorySize, GEMM_SMEM);

    dim3 tb(32, 8);
    transpose_tf32<<<dim3(DD/32, DD/32), tb>>>(Wq, wqkvt,           DD, DD);
    transpose_tf32<<<dim3(DD/32, DD/32), tb>>>(Wk, wqkvt + DD*DD,   DD, DD);
    transpose_tf32<<<dim3(DD/32, DD/32), tb>>>(Wv, wqkvt + 2*DD*DD, DD, DD);
    transpose_tf32<<<dim3(FF/32, DD/32), tb>>>(W1, w1t, DD, FF);
    transpose_tf32<<<dim3(DD/32, FF/32), tb>>>(W2, w2t, FF, DD);
    concat_bias<<<NQKV/256, 256>>>(bq, bk, bv, bqkv);

    // 1. h = LN(x)  (tf32-rounded: feeds QKV GEMM)
    ln_kernel<true><<<MM, 256>>>(x, nullptr, ln_in_g, ln_in_b, hbuf);

    // 2. fused QKV: [M,1536] = h @ [Wq|Wk|Wv]
    tc_gemm<false, false><<<dim3(NQKV/128, MM/128), 256, GEMM_SMEM>>>(
        hbuf, wqkvt, bqkv, qkvbuf, MM, NQKV, DD);

    // 3. masked flash attention (tensor cores)
    attn_tc<<<dim3(TT/QTILE, HH, BB), 256, ATTN_SMEM>>>(qkvbuf, mask, attnbuf);

    // 4. a = LN1(attn + x)  (tf32-rounded: feeds FFN1)
    ln_kernel<true><<<MM, 256>>>(attnbuf, x, ln1_g, ln1_b, abuf);

    // 5. FFN
    tc_gemm<true, true><<<dim3(FF/128, MM/128), 256, GEMM_SMEM>>>(
        abuf, w1t, b1, f1buf, MM, FF, DD);
    tc_gemm<false, false><<<dim3(DD/128, MM/128), 256, GEMM_SMEM>>>(
        f1buf, w2t, b2, f2buf, MM, DD, FF);

    // 6. out = LN2(f + a)
    ln_kernel<false><<<MM, 256>>>(f2buf, abuf, ln2_g, ln2_b, out);
}

// round 10
// speedup vs baseline: 3.6844x; 1.3674x over previous
#include <cuda_runtime.h>
#include <cuda_fp16.h>
#include <cstdint>
#include <math.h>

#define BB 8
#define TT 1024
#define DD 512
#define HH 8
#define FF 2048
#define MM (BB*TT)   // 8192 rows
#define NQKV (3*DD)  // 1536

// ---------------- scratch (allocation-free: __device__ globals) ----------------
__device__ __half g_h16[MM*DD];       // LN(x) in fp16 (feeds QKV GEMM)
__device__ __half g_qkv16[MM*NQKV];   // fused QKV output, fp16
__device__ float  g_attn[MM*DD];      // attention output (pre-residual)
__device__ float  g_a[MM*DD];         // LN1(attn + x) fp32 (LN2 residual)
__device__ __half g_a16[MM*DD];       // LN1 fp16 (feeds FFN1)
__device__ __half g_f116[MM*FF];      // relu(a@W1+b1) fp16 (feeds FFN2)
__device__ float  g_f2[MM*DD];        // f1@W2+b2
__device__ __half g_Wqkvt16[NQKV*DD]; // [1536,512] fp16, rows q|k|v, transposed
__device__ __half g_W1t16[FF*DD];     // [2048,512] fp16
__device__ __half g_W2t16[DD*FF];     // [512,2048] fp16
__device__ float  g_bqkv[NQKV];

// ---------------- helpers ----------------
__device__ __forceinline__ uint32_t s2u(const void* p) {
    uint32_t a;
    asm("{ .reg .u64 t; cvta.to.shared.u64 t, %1; cvt.u32.u64 %0, t; }" : "=r"(a) : "l"(p));
    return a;
}
__device__ __forceinline__ float cvt_tf32f(float x) {
    uint32_t r; asm("cvt.rna.tf32.f32 %0, %1;" : "=r"(r) : "f"(x));
    return __uint_as_float(r);
}
__device__ __forceinline__ void cp_async16(uint32_t saddr, const void* gaddr) {
    asm volatile("cp.async.ca.shared.global [%0], [%1], 16;" :: "r"(saddr), "l"(gaddr));
}
__device__ __forceinline__ void cp_commit() {
    asm volatile("cp.async.commit_group;" ::: "memory");
}
__device__ __forceinline__ void cp_wait1() {
    asm volatile("cp.async.wait_group 1;" ::: "memory");
}
__device__ __forceinline__ void cp_wait0() {
    asm volatile("cp.async.wait_group 0;" ::: "memory");
}
// fp16 m16n8k16, fp32 accumulate
__device__ __forceinline__ void mma_f16(float* c, const uint32_t* a, const uint32_t* b) {
    asm volatile(
        "mma.sync.aligned.m16n8k16.row.col.f32.f16.f16.f32 "
        "{%0,%1,%2,%3}, {%4,%5,%6,%7}, {%8,%9}, {%0,%1,%2,%3};"
        : "+f"(c[0]), "+f"(c[1]), "+f"(c[2]), "+f"(c[3])
        : "r"(a[0]), "r"(a[1]), "r"(a[2]), "r"(a[3]), "r"(b[0]), "r"(b[1]));
}
// tf32 m16n8k8 (attention)
__device__ __forceinline__ void mma_tf32(float* c, const uint32_t* a, const uint32_t* b) {
    asm volatile(
        "mma.sync.aligned.m16n8k8.row.col.f32.tf32.tf32.f32 "
        "{%0,%1,%2,%3}, {%4,%5,%6,%7}, {%8,%9}, {%0,%1,%2,%3};"
        : "+f"(c[0]), "+f"(c[1]), "+f"(c[2]), "+f"(c[3])
        : "r"(a[0]), "r"(a[1]), "r"(a[2]), "r"(a[3]), "r"(b[0]), "r"(b[1]));
}

// ---------------- weight transpose + fp16 convert: W[R,N] -> Wt[N,R] ------------
__global__ void transpose_f16(const float* __restrict__ W, __half* __restrict__ Wt,
                              int R, int N) {
    __shared__ float tile[32][33];
    int rb = blockIdx.y * 32, nb = blockIdx.x * 32;
    int tx = threadIdx.x, ty = threadIdx.y;   // 32 x 8
    #pragma unroll
    for (int i = 0; i < 32; i += 8)
        tile[ty + i][tx] = W[(size_t)(rb + ty + i) * N + nb + tx];
    __syncthreads();
    #pragma unroll
    for (int i = 0; i < 32; i += 8)
        Wt[(size_t)(nb + ty + i) * R + rb + tx] = __float2half_rn(tile[tx][ty + i]);
}

__global__ void concat_bias(const float* __restrict__ bq, const float* __restrict__ bk,
                            const float* __restrict__ bv, float* __restrict__ o) {
    int t = blockIdx.x * 256 + threadIdx.x;
    if (t < NQKV)
        o[t] = t < 512 ? bq[t] : (t < 1024 ? bk[t - 512] : bv[t - 1024]);
}

// ---------------- fp16 mma GEMM: C[M,N] = A[M,K] @ Bt[N,K]^T + bias -------------
// 128x128 CTA tile, KC=64 halfs, 2-stage cp.async, 256 threads (8 warps 2x4).
// b32 pitch 36 (72 halfs): fragment LDS addr = 4g+tg mod 32 -> conflict-free.
#define KC16 64
#define P32 36                              // b32 pitch per row
#define STG_HALFS (2 * 128 * 2 * P32)       // A+B per stage, halfs
#define STG_BYTES (STG_HALFS * 2)           // 36864 B
#define GEMM_SMEM (2 * STG_BYTES)           // 73728 B

template<bool RELU, bool OUTHALF>
__global__ __launch_bounds__(256)
void tc_gemm16(const __half* __restrict__ A, const __half* __restrict__ Bt,
               const float* __restrict__ bias, void* __restrict__ Cout,
               int M, int N, int K)
{
    extern __shared__ __half smh[];
    uint32_t sbase = s2u(smh);

    int t = threadIdx.x;
    int wid = t >> 5, lane = t & 31;
    int g = lane >> 2, tg = lane & 3;
    int wm = wid & 1, wn = wid >> 1;
    int brow = blockIdx.y * 128, bcol = blockIdx.x * 128;

    float acc[4][4][4];
    #pragma unroll
    for (int i = 0; i < 4; i++)
        #pragma unroll
        for (int j = 0; j < 4; j++)
            #pragma unroll
            for (int r = 0; r < 4; r++) acc[i][j][r] = 0.f;

    int nk = K / KC16;

    auto load_stage = [&](int s, int c) {
        uint32_t sA = sbase + (uint32_t)s * STG_BYTES;
        uint32_t sB = sA + 128u * P32 * 4u;
        const __half* ag = A + (size_t)brow * K + c * KC16;
        const __half* bg = Bt + (size_t)bcol * K + c * KC16;
        #pragma unroll
        for (int i = 0; i < 4; i++) {
            int idx = t + i * 256;            // 1024 chunks of 8 halfs (16B)
            int r = idx >> 3, cg = idx & 7;
            cp_async16(sA + (uint32_t)(r * 144 + cg * 16),
                       ag + (size_t)r * K + cg * 8);
            cp_async16(sB + (uint32_t)(r * 144 + cg * 16),
                       bg + (size_t)r * K + cg * 8);
        }
        cp_commit();
    };

    load_stage(0, 0);

    for (int c = 0; c < nk; c++) {
        if (c + 1 < nk) load_stage((c + 1) & 1, c + 1);
        if (c + 1 < nk) cp_wait1(); else cp_wait0();
        __syncthreads();

        const uint32_t* As32 = (const uint32_t*)(smh + (size_t)(c & 1) * STG_HALFS);
        const uint32_t* Bs32 = As32 + 128 * P32;

        #pragma unroll
        for (int ks = 0; ks < 4; ks++) {      // k0 = ks*16 halfs = ks*8 b32
            int k0 = ks * 8;
            uint32_t af[4][4], bf[4][2];
            #pragma unroll
            for (int mt = 0; mt < 4; mt++) {
                int r0 = wm * 64 + mt * 16 + g;
                af[mt][0] = As32[r0 * P32 + k0 + tg];
                af[mt][1] = As32[(r0 + 8) * P32 + k0 + tg];
                af[mt][2] = As32[r0 * P32 + k0 + 4 + tg];
                af[mt][3] = As32[(r0 + 8) * P32 + k0 + 4 + tg];
            }
            #pragma unroll
            for (int nt = 0; nt < 4; nt++) {
                int n0 = wn * 32 + nt * 8 + g;
                bf[nt][0] = Bs32[n0 * P32 + k0 + tg];
                bf[nt][1] = Bs32[n0 * P32 + k0 + 4 + tg];
            }
            #pragma unroll
            for (int mt = 0; mt < 4; mt++)
                #pragma unroll
                for (int nt = 0; nt < 4; nt++)
                    mma_f16(acc[mt][nt], af[mt], bf[nt]);
        }
        __syncthreads();
    }

    #pragma unroll
    for (int mt = 0; mt < 4; mt++) {
        int r0 = brow + wm * 64 + mt * 16 + g;
        #pragma unroll
        for (int nt = 0; nt < 4; nt++) {
            int col = bcol + wn * 32 + nt * 8 + tg * 2;
            float2 bv2 = *(const float2*)(bias + col);
            float v0 = acc[mt][nt][0] + bv2.x;
            float v1 = acc[mt][nt][1] + bv2.y;
            float v2 = acc[mt][nt][2] + bv2.x;
            float v3 = acc[mt][nt][3] + bv2.y;
            if (RELU) {
                v0 = fmaxf(v0, 0.f); v1 = fmaxf(v1, 0.f);
                v2 = fmaxf(v2, 0.f); v3 = fmaxf(v3, 0.f);
            }
            if (OUTHALF) {
                __half* C16 = (__half*)Cout;
                *(__half2*)(C16 + (size_t)r0 * N + col) =
                    __floats2half2_rn(v0, v1);
                *(__half2*)(C16 + (size_t)(r0 + 8) * N + col) =
                    __floats2half2_rn(v2, v3);
            } else {
                float* C = (float*)Cout;
                *(float2*)(C + (size_t)r0 * N + col)       = make_float2(v0, v1);
                *(float2*)(C + (size_t)(r0 + 8) * N + col) = make_float2(v2, v3);
            }
        }
    }
}

// ---------------- LayerNorm (fused residual; fp32 and/or fp16 outputs) ----------
template<bool W32, bool W16>
__global__ __launch_bounds__(256) void ln_kernel(
    const float* __restrict__ in1, const float* __restrict__ in2,
    const float* __restrict__ gam, const float* __restrict__ bet,
    float* __restrict__ out32, __half* __restrict__ out16)
{
    int row = blockIdx.x;
    int t = threadIdx.x;
    const float* p1 = in1 + (size_t)row * DD;
    float v0 = p1[t];
    float v1 = p1[t + 256];
    if (in2) {
        const float* p2 = in2 + (size_t)row * DD;
        v0 += p2[t];
        v1 += p2[t + 256];
    }
    __shared__ float red[8];
    float s = v0 + v1;
    #pragma unroll
    for (int o = 16; o > 0; o >>= 1) s += __shfl_xor_sync(0xffffffffu, s, o);
    if ((t & 31) == 0) red[t >> 5] = s;
    __syncthreads();
    float tot = 0.f;
    #pragma unroll
    for (int i = 0; i < 8; i++) tot += red[i];
    float mu = tot * (1.0f / DD);
    float d0 = v0 - mu, d1 = v1 - mu;
    s = d0 * d0 + d1 * d1;
    #pragma unroll
    for (int o = 16; o > 0; o >>= 1) s += __shfl_xor_sync(0xffffffffu, s, o);
    __syncthreads();
    if ((t & 31) == 0) red[t >> 5] = s;
    __syncthreads();
    tot = 0.f;
    #pragma unroll
    for (int i = 0; i < 8; i++) tot += red[i];
    float r = rsqrtf(tot * (1.0f / DD) + 1e-3f);
    float o0 = d0 * r * gam[t]       + bet[t];
    float o1 = d1 * r * gam[t + 256] + bet[t + 256];
    if (W32) {
        out32[(size_t)row * DD + t]       = o0;
        out32[(size_t)row * DD + t + 256] = o1;
    }
    if (W16) {
        out16[(size_t)row * DD + t]       = __float2half_rn(o0);
        out16[(size_t)row * DD + t + 256] = __float2half_rn(o1);
    }
}

// ---------------- tensor-core flash attention (tf32 mma, fp16 qkv input) --------
// CTA: 128 queries x 64 keys, DK=64, 256 threads (8 warps; warp w = query rows w*16).
// SMEM pitch 68 floats: fragment reads land on 32 distinct banks (68 mod 32 = 4).
#define QTILE 128
#define KTILE 64
#define AP 68
#define ATTN_SMEM ((QTILE + KTILE + KTILE + QTILE) * AP * (int)sizeof(float))  // 104448

__global__ __launch_bounds__(256) void attn_tc(
    const __half* __restrict__ QKV, const float* __restrict__ mask,
    float* __restrict__ O)
{
    extern __shared__ float smf[];
    float* Qs = smf;                    // [128][68] (rows q, cols d)
    float* Ks = Qs + QTILE * AP;        // [64][68]  (rows k, cols d)
    float* Vt = Ks + KTILE * AP;        // [64][68]  (rows d, cols s) -- transposed
    float* Ps = Vt + KTILE * AP;        // [128][68] (rows q, cols s)

    int b = blockIdx.z, h = blockIdx.y, qt = blockIdx.x;
    int t = threadIdx.x;
    int w = t >> 5, lane = t & 31;
    int g = lane >> 2, tg = lane & 3;

    const __half* qptr  = QKV + ((size_t)(b * TT) + qt * QTILE) * NQKV + h * 64;
    const __half* kptr0 = QKV + (size_t)(b * TT) * NQKV + h * 64 + 512;
    const __half* vptr0 = QKV + (size_t)(b * TT) * NQKV + h * 64 + 1024;

    // load Q tile (fp16 -> fp32, exactly tf32-representable)
    #pragma unroll
    for (int i = 0; i < 4; i++) {
        int idx = t + i * 256;              // 1024 chunks of 8 halfs
        int r = idx >> 3, c = idx & 7;
        uint4 raw = *(const uint4*)(qptr + (size_t)r * NQKV + c * 8);
        const __half2* h2 = (const __half2*)&raw;
        float* dst = Qs + r * AP + c * 8;
        #pragma unroll
        for (int j = 0; j < 4; j++) {
            float2 f = __half22float2(h2[j]);
            dst[2*j] = f.x; dst[2*j+1] = f.y;
        }
    }

    float m0 = -1e30f, m1 = -1e30f, l0 = 0.f, l1 = 0.f;
    float oacc[8][4];
    #pragma unroll
    for (int dt = 0; dt < 8; dt++)
        #pragma unroll
        for (int r = 0; r < 4; r++) oacc[dt][r] = 0.f;

    const float* mrow0 = mask + ((size_t)b * TT + qt * QTILE + w * 16 + g) * TT;
    const float* mrow1 = mrow0 + 8 * TT;

    for (int kt = 0; kt < TT / KTILE; kt++) {
        // ---- load K (rows k, cols d) and V transposed (rows d, cols s) ----
        #pragma unroll
        for (int i = 0; i < 2; i++) {
            int idx = t + i * 256;          // 512 chunks of 8 halfs
            int r = idx >> 3, c = idx & 7;
            uint4 raw = *(const uint4*)(kptr0 + (size_t)(kt * KTILE + r) * NQKV + c * 8);
            const __half2* h2 = (const __half2*)&raw;
            float* dst = Ks + r * AP + c * 8;
            #pragma unroll
            for (int j = 0; j < 4; j++) {
                float2 f = __half22float2(h2[j]);
                dst[2*j] = f.x; dst[2*j+1] = f.y;
            }
        }
        #pragma unroll
        for (int i = 0; i < 4; i++) {
            int idx = t + i * 256;          // 64 d x 16 s-groups
            int d = idx & 63, s0 = (idx >> 6) * 4;
            const __half* vp = vptr0 + (size_t)(kt * KTILE + s0) * NQKV + d;
            float4 w4 = make_float4(__half2float(vp[0]),
                                    __half2float(vp[NQKV]),
                                    __half2float(vp[2 * NQKV]),
                                    __half2float(vp[3 * NQKV]));
            *(float4*)&Vt[d * AP + s0] = w4;
        }
        __syncthreads();

        // ---- S = Q K^T ----
        float sacc[8][4];
        #pragma unroll
        for (int nt = 0; nt < 8; nt++)
            #pragma unroll
            for (int r = 0; r < 4; r++) sacc[nt][r] = 0.f;

        #pragma unroll
        for (int kc = 0; kc < 8; kc++) {
            int k0 = kc * 8;
            int r0 = w * 16 + g;
            uint32_t af[4];
            af[0] = __float_as_uint(Qs[r0 * AP + k0 + tg]);
            af[1] = __float_as_uint(Qs[(r0 + 8) * AP + k0 + tg]);
            af[2] = __float_as_uint(Qs[r0 * AP + k0 + tg + 4]);
            af[3] = __float_as_uint(Qs[(r0 + 8) * AP + k0 + tg + 4]);
            #pragma unroll
            for (int nt = 0; nt < 8; nt++) {
                uint32_t bf[2];
                bf[0] = __float_as_uint(Ks[(nt * 8 + g) * AP + k0 + tg]);
                bf[1] = __float_as_uint(Ks[(nt * 8 + g) * AP + k0 + tg + 4]);
                mma_tf32(sacc[nt], af, bf);
            }
        }

        // ---- scale + mask + online softmax on fragments ----
        const float* mk0 = mrow0 + kt * KTILE;
        const float* mk1 = mrow1 + kt * KTILE;
        float rm0 = -1e30f, rm1 = -1e30f;
        #pragma unroll
        for (int nt = 0; nt < 8; nt++) {
            float2 a0 = *(const float2*)(mk0 + nt * 8 + 2 * tg);
            float2 a1 = *(const float2*)(mk1 + nt * 8 + 2 * tg);
            sacc[nt][0] = sacc[nt][0] * 0.125f + (a0.x - 1.f) * 1e9f;
            sacc[nt][1] = sacc[nt][1] * 0.125f + (a0.y - 1.f) * 1e9f;
            sacc[nt][2] = sacc[nt][2] * 0.125f + (a1.x - 1.f) * 1e9f;
            sacc[nt][3] = sacc[nt][3] * 0.125f + (a1.y - 1.f) * 1e9f;
            rm0 = fmaxf(rm0, fmaxf(sacc[nt][0], sacc[nt][1]));
            rm1 = fmaxf(rm1, fmaxf(sacc[nt][2], sacc[nt][3]));
        }
        rm0 = fmaxf(rm0, __shfl_xor_sync(0xffffffffu, rm0, 1));
        rm0 = fmaxf(rm0, __shfl_xor_sync(0xffffffffu, rm0, 2));
        rm1 = fmaxf(rm1, __shfl_xor_sync(0xffffffffu, rm1, 1));
        rm1 = fmaxf(rm1, __shfl_xor_sync(0xffffffffu, rm1, 2));

        float mn0 = fmaxf(m0, rm0), mn1 = fmaxf(m1, rm1);
        float corr0 = __expf(m0 - mn0), corr1 = __expf(m1 - mn1);
        m0 = mn0; m1 = mn1;

        float rl0 = 0.f, rl1 = 0.f;
        int q0 = w * 16 + g;
        #pragma unroll
        for (int nt = 0; nt < 8; nt++) {
            float p0 = __expf(sacc[nt][0] - mn0);
            float p1 = __expf(sacc[nt][1] - mn0);
            float p2 = __expf(sacc[nt][2] - mn1);
            float p3 = __expf(sacc[nt][3] - mn1);
            rl0 += p0 + p1;
            rl1 += p2 + p3;
            *(float2*)&Ps[q0 * AP + nt * 8 + 2 * tg] =
                make_float2(cvt_tf32f(p0), cvt_tf32f(p1));
            *(float2*)&Ps[(q0 + 8) * AP + nt * 8 + 2 * tg] =
                make_float2(cvt_tf32f(p2), cvt_tf32f(p3));
        }
        rl0 += __shfl_xor_sync(0xffffffffu, rl0, 1);
        rl0 += __shfl_xor_sync(0xffffffffu, rl0, 2);
        rl1 += __shfl_xor_sync(0xffffffffu, rl1, 1);
        rl1 += __shfl_xor_sync(0xffffffffu, rl1, 2);
        l0 = l0 * corr0 + rl0;
        l1 = l1 * corr1 + rl1;

        #pragma unroll
        for (int dt = 0; dt < 8; dt++) {
            oacc[dt][0] *= corr0; oacc[dt][1] *= corr0;
            oacc[dt][2] *= corr1; oacc[dt][3] *= corr1;
        }
        __syncwarp();

        // ---- O += P @ V  (A = Ps rows, B = Vt[d][s]) ----
        #pragma unroll
        for (int kc = 0; kc < 8; kc++) {
            int k0 = kc * 8;
            uint32_t af[4];
            af[0] = __float_as_uint(Ps[q0 * AP + k0 + tg]);
            af[1] = __float_as_uint(Ps[(q0 + 8) * AP + k0 + tg]);
            af[2] = __float_as_uint(Ps[q0 * AP + k0 + tg + 4]);
            af[3] = __float_as_uint(Ps[(q0 + 8) * AP + k0 + tg + 4]);
            #pragma unroll
            for (int dt = 0; dt < 8; dt++) {
                uint32_t bf[2];
                bf[0] = __float_as_uint(Vt[(dt * 8 + g) * AP + k0 + tg]);
                bf[1] = __float_as_uint(Vt[(dt * 8 + g) * AP + k0 + tg + 4]);
                mma_tf32(oacc[dt], af, bf);
            }
        }
        __syncthreads();
    }

    // ---- epilogue: divide by l, write out ----
    float inv0 = 1.0f / l0, inv1 = 1.0f / l1;
    float* optr = O + ((size_t)(b * TT) + qt * QTILE + w * 16 + g) * DD + h * 64;
    #pragma unroll
    for (int dt = 0; dt < 8; dt++) {
        int col = dt * 8 + 2 * tg;
        *(float2*)(optr + col) =
            make_float2(oacc[dt][0] * inv0, oacc[dt][1] * inv0);
        *(float2*)(optr + 8 * DD + col) =
            make_float2(oacc[dt][2] * inv1, oacc[dt][3] * inv1);
    }
}

// ---------------- launch ----------------
extern "C" void kernel_launch(void* const* d_in, const int* in_sizes, int n_in,
                              void* d_out, int out_size)
{
    const float* x       = (const float*)d_in[0];
    const float* mask    = (const float*)d_in[1];
    const float* ln_in_g = (const float*)d_in[2];
    const float* ln_in_b = (const float*)d_in[3];
    const float* Wq = (const float*)d_in[4];
    const float* bq = (const float*)d_in[5];
    const float* Wk = (const float*)d_in[6];
    const float* bk = (const float*)d_in[7];
    const float* Wv = (const float*)d_in[8];
    const float* bv = (const float*)d_in[9];
    const float* ln1_g = (const float*)d_in[10];
    const float* ln1_b = (const float*)d_in[11];
    const float* W1 = (const float*)d_in[12];
    const float* b1 = (const float*)d_in[13];
    const float* W2 = (const float*)d_in[14];
    const float* b2 = (const float*)d_in[15];
    const float* ln2_g = (const float*)d_in[16];
    const float* ln2_b = (const float*)d_in[17];
    float* out = (float*)d_out;

    __half *h16, *qkv16, *a16, *f116, *wqkvt, *w1t, *w2t;
    float *attnbuf, *abuf, *f2buf, *bqkv;
    cudaGetSymbolAddress((void**)&h16,     g_h16);
    cudaGetSymbolAddress((void**)&qkv16,   g_qkv16);
    cudaGetSymbolAddress((void**)&attnbuf, g_attn);
    cudaGetSymbolAddress((void**)&abuf,    g_a);
    cudaGetSymbolAddress((void**)&a16,     g_a16);
    cudaGetSymbolAddress((void**)&f116,    g_f116);
    cudaGetSymbolAddress((void**)&f2buf,   g_f2);
    cudaGetSymbolAddress((void**)&wqkvt,   g_Wqkvt16);
    cudaGetSymbolAddress((void**)&w1t,     g_W1t16);
    cudaGetSymbolAddress((void**)&w2t,     g_W2t16);
    cudaGetSymbolAddress((void**)&bqkv,    g_bqkv);

    cudaFuncSetAttribute(attn_tc,
                         cudaFuncAttributeMaxDynamicSharedMemorySize, ATTN_SMEM);
    cudaFuncSetAttribute(tc_gemm16<false, true>,
                         cudaFuncAttributeMaxDynamicSharedMemorySize, GEMM_SMEM);
    cudaFuncSetAttribute(tc_gemm16<true, true>,
                         cudaFuncAttributeMaxDynamicSharedMemorySize, GEMM_SMEM);
    cudaFuncSetAttribute(tc_gemm16<false, false>,
                         cudaFuncAttributeMaxDynamicSharedMemorySize, GEMM_SMEM);

    dim3 tb(32, 8);
    transpose_f16<<<dim3(DD/32, DD/32), tb>>>(Wq, wqkvt,           DD, DD);
    transpose_f16<<<dim3(DD/32, DD/32), tb>>>(Wk, wqkvt + DD*DD,   DD, DD);
    transpose_f16<<<dim3(DD/32, DD/32), tb>>>(Wv, wqkvt + 2*DD*DD, DD, DD);
    transpose_f16<<<dim3(FF/32, DD/32), tb>>>(W1, w1t, DD, FF);
    transpose_f16<<<dim3(DD/32, FF/32), tb>>>(W2, w2t, FF, DD);
    concat_bias<<<NQKV/256, 256>>>(bq, bk, bv, bqkv);

    // 1. h = LN(x) -> fp16 (feeds QKV GEMM only)
    ln_kernel<false, true><<<MM, 256>>>(x, nullptr, ln_in_g, ln_in_b, nullptr, h16);

    // 2. fused QKV: [M,1536] fp16 = h @ [Wq|Wk|Wv]
    tc_gemm16<false, true><<<dim3(NQKV/128, MM/128), 256, GEMM_SMEM>>>(
        h16, wqkvt, bqkv, qkv16, MM, NQKV, DD);

    // 3. masked flash attention (tensor cores, fp16 inputs)
    attn_tc<<<dim3(TT/QTILE, HH, BB), 256, ATTN_SMEM>>>(qkv16, mask, attnbuf);

    // 4. a = LN1(attn + x) -> fp32 (LN2 residual) + fp16 (FFN1 input)
    ln_kernel<true, true><<<MM, 256>>>(attnbuf, x, ln1_g, ln1_b, abuf, a16);

    // 5. FFN: f1 = relu(a@W1+b1) fp16; f2 = f1@W2+b2 fp32
    tc_gemm16<true, true><<<dim3(FF/128, MM/128), 256, GEMM_SMEM>>>(
        a16, w1t, b1, f116, MM, FF, DD);
    tc_gemm16<false, false><<<dim3(DD/128, MM/128), 256, GEMM_SMEM>>>(
        f116, w2t, b2, f2buf, MM, DD, FF);

    // 6. out = LN2(f + a)
    ln_kernel<true, false><<<MM, 256>>>(f2buf, abuf, ln2_g, ln2_b, out, nullptr);
}

// round 11
// speedup vs baseline: 4.1245x; 1.1194x over previous
#include <cuda_runtime.h>
#include <cuda_fp16.h>
#include <cstdint>
#include <math.h>

#define BB 8
#define TT 1024
#define DD 512
#define HH 8
#define FF 2048
#define MM (BB*TT)   // 8192 rows
#define NQKV (3*DD)  // 1536

// ---------------- scratch (allocation-free: __device__ globals) ----------------
__device__ __half g_h16[MM*DD];       // LN(x) in fp16 (feeds QKV GEMM)
__device__ __half g_qkv16[MM*NQKV];   // fused QKV output, fp16
__device__ float  g_attn[MM*DD];      // attention output (pre-residual)
__device__ float  g_a[MM*DD];         // LN1(attn + x) fp32 (LN2 residual)
__device__ __half g_a16[MM*DD];       // LN1 fp16 (feeds FFN1)
__device__ __half g_f116[MM*FF];      // relu(a@W1+b1) fp16 (feeds FFN2)
__device__ float  g_f2[MM*DD];        // f1@W2+b2
__device__ __half g_Wqkvt16[NQKV*DD]; // [1536,512] fp16, rows q|k|v, transposed
__device__ __half g_W1t16[FF*DD];     // [2048,512] fp16
__device__ __half g_W2t16[DD*FF];     // [512,2048] fp16
__device__ float  g_bqkv[NQKV];

// ---------------- helpers ----------------
__device__ __forceinline__ uint32_t s2u(const void* p) {
    uint32_t a;
    asm("{ .reg .u64 t; cvta.to.shared.u64 t, %1; cvt.u32.u64 %0, t; }" : "=r"(a) : "l"(p));
    return a;
}
__device__ __forceinline__ void cp_async16(uint32_t saddr, const void* gaddr) {
    asm volatile("cp.async.ca.shared.global [%0], [%1], 16;" :: "r"(saddr), "l"(gaddr));
}
__device__ __forceinline__ void cp_commit() {
    asm volatile("cp.async.commit_group;" ::: "memory");
}
__device__ __forceinline__ void cp_wait1() {
    asm volatile("cp.async.wait_group 1;" ::: "memory");
}
__device__ __forceinline__ void cp_wait0() {
    asm volatile("cp.async.wait_group 0;" ::: "memory");
}
// fp16 m16n8k16, fp32 accumulate
__device__ __forceinline__ void mma_f16(float* c, const uint32_t* a, const uint32_t* b) {
    asm volatile(
        "mma.sync.aligned.m16n8k16.row.col.f32.f16.f16.f32 "
        "{%0,%1,%2,%3}, {%4,%5,%6,%7}, {%8,%9}, {%0,%1,%2,%3};"
        : "+f"(c[0]), "+f"(c[1]), "+f"(c[2]), "+f"(c[3])
        : "r"(a[0]), "r"(a[1]), "r"(a[2]), "r"(a[3]), "r"(b[0]), "r"(b[1]));
}
__device__ __forceinline__ uint32_t packh2(float a, float b) {
    __half2 h = __floats2half2_rn(a, b);
    return *(uint32_t*)&h;
}

// ---------------- fused weight transpose + fp16: all 5 matrices in one launch ---
// tiles: Wq 256 | Wk 256 | Wv 256 | W1 1024 | W2 1024  => 2816 blocks
__global__ void transpose_all(const float* __restrict__ Wq, const float* __restrict__ Wk,
                              const float* __restrict__ Wv, const float* __restrict__ W1,
                              const float* __restrict__ W2,
                              __half* __restrict__ wqkvt, __half* __restrict__ w1t,
                              __half* __restrict__ w2t)
{
    __shared__ float tile[32][33];
    int bid = blockIdx.x;
    const float* W; __half* Wt; int R, N, tl;
    if (bid < 256)       { W = Wq; Wt = wqkvt;             R = DD; N = DD; tl = bid; }
    else if (bid < 512)  { W = Wk; Wt = wqkvt + DD*DD;     R = DD; N = DD; tl = bid - 256; }
    else if (bid < 768)  { W = Wv; Wt = wqkvt + 2*DD*DD;   R = DD; N = DD; tl = bid - 512; }
    else if (bid < 1792) { W = W1; Wt = w1t;               R = DD; N = FF; tl = bid - 768; }
    else                 { W = W2; Wt = w2t;               R = FF; N = DD; tl = bid - 1792; }
    int ntx = N / 32;
    int nb = (tl % ntx) * 32, rb = (tl / ntx) * 32;
    int tx = threadIdx.x, ty = threadIdx.y;   // 32 x 8
    #pragma unroll
    for (int i = 0; i < 32; i += 8)
        tile[ty + i][tx] = W[(size_t)(rb + ty + i) * N + nb + tx];
    __syncthreads();
    #pragma unroll
    for (int i = 0; i < 32; i += 8)
        Wt[(size_t)(nb + ty + i) * R + rb + tx] = __float2half_rn(tile[tx][ty + i]);
}

__global__ void concat_bias(const float* __restrict__ bq, const float* __restrict__ bk,
                            const float* __restrict__ bv, float* __restrict__ o) {
    int t = blockIdx.x * 256 + threadIdx.x;
    if (t < NQKV)
        o[t] = t < 512 ? bq[t] : (t < 1024 ? bk[t - 512] : bv[t - 1024]);
}

// ---------------- fp16 mma GEMM: C[M,N] = A[M,K] @ Bt[N,K]^T + bias -------------
#define KC16 64
#define P32 36                              // b32 pitch per row
#define STG_HALFS (2 * 128 * 2 * P32)
#define STG_BYTES (STG_HALFS * 2)           // 36864 B
#define GEMM_SMEM (2 * STG_BYTES)           // 73728 B

template<bool RELU, bool OUTHALF>
__global__ __launch_bounds__(256)
void tc_gemm16(const __half* __restrict__ A, const __half* __restrict__ Bt,
               const float* __restrict__ bias, void* __restrict__ Cout,
               int M, int N, int K)
{
    extern __shared__ __half smh[];
    uint32_t sbase = s2u(smh);

    int t = threadIdx.x;
    int wid = t >> 5, lane = t & 31;
    int g = lane >> 2, tg = lane & 3;
    int wm = wid & 1, wn = wid >> 1;
    int brow = blockIdx.y * 128, bcol = blockIdx.x * 128;

    float acc[4][4][4];
    #pragma unroll
    for (int i = 0; i < 4; i++)
        #pragma unroll
        for (int j = 0; j < 4; j++)
            #pragma unroll
            for (int r = 0; r < 4; r++) acc[i][j][r] = 0.f;

    int nk = K / KC16;

    auto load_stage = [&](int s, int c) {
        uint32_t sA = sbase + (uint32_t)s * STG_BYTES;
        uint32_t sB = sA + 128u * P32 * 4u;
        const __half* ag = A + (size_t)brow * K + c * KC16;
        const __half* bg = Bt + (size_t)bcol * K + c * KC16;
        #pragma unroll
        for (int i = 0; i < 4; i++) {
            int idx = t + i * 256;
            int r = idx >> 3, cg = idx & 7;
            cp_async16(sA + (uint32_t)(r * 144 + cg * 16),
                       ag + (size_t)r * K + cg * 8);
            cp_async16(sB + (uint32_t)(r * 144 + cg * 16),
                       bg + (size_t)r * K + cg * 8);
        }
        cp_commit();
    };

    load_stage(0, 0);

    for (int c = 0; c < nk; c++) {
        if (c + 1 < nk) load_stage((c + 1) & 1, c + 1);
        if (c + 1 < nk) cp_wait1(); else cp_wait0();
        __syncthreads();

        const uint32_t* As32 = (const uint32_t*)(smh + (size_t)(c & 1) * STG_HALFS);
        const uint32_t* Bs32 = As32 + 128 * P32;

        #pragma unroll
        for (int ks = 0; ks < 4; ks++) {
            int k0 = ks * 8;
            uint32_t af[4][4], bf[4][2];
            #pragma unroll
            for (int mt = 0; mt < 4; mt++) {
                int r0 = wm * 64 + mt * 16 + g;
                af[mt][0] = As32[r0 * P32 + k0 + tg];
                af[mt][1] = As32[(r0 + 8) * P32 + k0 + tg];
                af[mt][2] = As32[r0 * P32 + k0 + 4 + tg];
                af[mt][3] = As32[(r0 + 8) * P32 + k0 + 4 + tg];
            }
            #pragma unroll
            for (int nt = 0; nt < 4; nt++) {
                int n0 = wn * 32 + nt * 8 + g;
                bf[nt][0] = Bs32[n0 * P32 + k0 + tg];
                bf[nt][1] = Bs32[n0 * P32 + k0 + 4 + tg];
            }
            #pragma unroll
            for (int mt = 0; mt < 4; mt++)
                #pragma unroll
                for (int nt = 0; nt < 4; nt++)
                    mma_f16(acc[mt][nt], af[mt], bf[nt]);
        }
        __syncthreads();
    }

    #pragma unroll
    for (int mt = 0; mt < 4; mt++) {
        int r0 = brow + wm * 64 + mt * 16 + g;
        #pragma unroll
        for (int nt = 0; nt < 4; nt++) {
            int col = bcol + wn * 32 + nt * 8 + tg * 2;
            float2 bv2 = *(const float2*)(bias + col);
            float v0 = acc[mt][nt][0] + bv2.x;
            float v1 = acc[mt][nt][1] + bv2.y;
            float v2 = acc[mt][nt][2] + bv2.x;
            float v3 = acc[mt][nt][3] + bv2.y;
            if (RELU) {
                v0 = fmaxf(v0, 0.f); v1 = fmaxf(v1, 0.f);
                v2 = fmaxf(v2, 0.f); v3 = fmaxf(v3, 0.f);
            }
            if (OUTHALF) {
                __half* C16 = (__half*)Cout;
                *(__half2*)(C16 + (size_t)r0 * N + col) =
                    __floats2half2_rn(v0, v1);
                *(__half2*)(C16 + (size_t)(r0 + 8) * N + col) =
                    __floats2half2_rn(v2, v3);
            } else {
                float* C = (float*)Cout;
                *(float2*)(C + (size_t)r0 * N + col)       = make_float2(v0, v1);
                *(float2*)(C + (size_t)(r0 + 8) * N + col) = make_float2(v2, v3);
            }
        }
    }
}

// ---------------- LayerNorm (fused residual; fp32 and/or fp16 outputs) ----------
template<bool W32, bool W16>
__global__ __launch_bounds__(256) void ln_kernel(
    const float* __restrict__ in1, const float* __restrict__ in2,
    const float* __restrict__ gam, const float* __restrict__ bet,
    float* __restrict__ out32, __half* __restrict__ out16)
{
    int row = blockIdx.x;
    int t = threadIdx.x;
    const float* p1 = in1 + (size_t)row * DD;
    float v0 = p1[t];
    float v1 = p1[t + 256];
    if (in2) {
        const float* p2 = in2 + (size_t)row * DD;
        v0 += p2[t];
        v1 += p2[t + 256];
    }
    __shared__ float red[8];
    float s = v0 + v1;
    #pragma unroll
    for (int o = 16; o > 0; o >>= 1) s += __shfl_xor_sync(0xffffffffu, s, o);
    if ((t & 31) == 0) red[t >> 5] = s;
    __syncthreads();
    float tot = 0.f;
    #pragma unroll
    for (int i = 0; i < 8; i++) tot += red[i];
    float mu = tot * (1.0f / DD);
    float d0 = v0 - mu, d1 = v1 - mu;
    s = d0 * d0 + d1 * d1;
    #pragma unroll
    for (int o = 16; o > 0; o >>= 1) s += __shfl_xor_sync(0xffffffffu, s, o);
    __syncthreads();
    if ((t & 31) == 0) red[t >> 5] = s;
    __syncthreads();
    tot = 0.f;
    #pragma unroll
    for (int i = 0; i < 8; i++) tot += red[i];
    float r = rsqrtf(tot * (1.0f / DD) + 1e-3f);
    float o0 = d0 * r * gam[t]       + bet[t];
    float o1 = d1 * r * gam[t + 256] + bet[t + 256];
    if (W32) {
        out32[(size_t)row * DD + t]       = o0;
        out32[(size_t)row * DD + t + 256] = o1;
    }
    if (W16) {
        out16[(size_t)row * DD + t]       = __float2half_rn(o0);
        out16[(size_t)row * DD + t + 256] = __float2half_rn(o1);
    }
}

// ---------------- tensor-core flash attention (fp16 mma m16n8k16) ---------------
// CTA: 128 queries x 64 keys, DK=64, 256 threads (8 warps; warp w = query rows w*16).
// All tiles fp16, b32 pitch 36: fragment LDS addr (4g+tg) spans 32 banks.
#define QTILE 128
#define KTILE 64
#define AP16 36   // b32 pitch = 72 halfs
#define ATTN_SMEM ((QTILE + KTILE + KTILE + QTILE) * AP16 * 4)   // 55296 B

__global__ __launch_bounds__(256) void attn_tc(
    const __half* __restrict__ QKV, const float* __restrict__ mask,
    float* __restrict__ O)
{
    extern __shared__ uint32_t sm32[];
    uint32_t* Qs = sm32;                     // [128][36] b32 (rows q, k-pairs)
    uint32_t* Ks = Qs + QTILE * AP16;        // [64][36]  (rows k, d-pairs)
    uint32_t* Vt = Ks + KTILE * AP16;        // [64][36]  (rows d, s-pairs) transposed
    uint32_t* Ps = Vt + KTILE * AP16;        // [128][36] (rows q, s-pairs)

    int b = blockIdx.z, h = blockIdx.y, qt = blockIdx.x;
    int t = threadIdx.x;
    int w = t >> 5, lane = t & 31;
    int g = lane >> 2, tg = lane & 3;

    const __half* qptr  = QKV + ((size_t)(b * TT) + qt * QTILE) * NQKV + h * 64;
    const __half* kptr0 = QKV + (size_t)(b * TT) * NQKV + h * 64 + 512;
    const __half* vptr0 = QKV + (size_t)(b * TT) * NQKV + h * 64 + 1024;

    // load Q tile fp16 (128 rows x 64 halfs = 8 chunks of 8 halfs per row)
    #pragma unroll
    for (int i = 0; i < 4; i++) {
        int idx = t + i * 256;               // 1024 chunks
        int r = idx >> 3, c = idx & 7;
        uint4 raw = *(const uint4*)(qptr + (size_t)r * NQKV + c * 8);
        *(uint4*)&Qs[r * AP16 + c * 4] = raw;
    }

    float m0 = -1e30f, m1 = -1e30f, l0 = 0.f, l1 = 0.f;
    float oacc[8][4];
    #pragma unroll
    for (int dt = 0; dt < 8; dt++)
        #pragma unroll
        for (int r = 0; r < 4; r++) oacc[dt][r] = 0.f;

    const float* mrow0 = mask + ((size_t)b * TT + qt * QTILE + w * 16 + g) * TT;
    const float* mrow1 = mrow0 + 8 * TT;
    int q0 = w * 16 + g;

    for (int kt = 0; kt < TT / KTILE; kt++) {
        // ---- load K (rows k, cols d) ----
        #pragma unroll
        for (int i = 0; i < 2; i++) {
            int idx = t + i * 256;           // 512 chunks
            int r = idx >> 3, c = idx & 7;
            uint4 raw = *(const uint4*)(kptr0 + (size_t)(kt * KTILE + r) * NQKV + c * 8);
            *(uint4*)&Ks[r * AP16 + c * 4] = raw;
        }
        // ---- load V transposed: Vt[d][s] ----
        #pragma unroll
        for (int i = 0; i < 4; i++) {
            int idx = t + i * 256;           // 64 d x 16 s-groups of 4
            int d = idx & 63, s0 = (idx >> 6) * 4;
            const __half* vp = vptr0 + (size_t)(kt * KTILE + s0) * NQKV + d;
            __half2 lo = __halves2half2(vp[0], vp[NQKV]);
            __half2 hi = __halves2half2(vp[2 * NQKV], vp[3 * NQKV]);
            uint2 pk;
            pk.x = *(uint32_t*)&lo; pk.y = *(uint32_t*)&hi;
            *(uint2*)&Vt[d * AP16 + (s0 >> 1)] = pk;
        }
        __syncthreads();

        // ---- S = Q K^T  (4 k-chunks of 16) ----
        float sacc[8][4];
        #pragma unroll
        for (int nt = 0; nt < 8; nt++)
            #pragma unroll
            for (int r = 0; r < 4; r++) sacc[nt][r] = 0.f;

        #pragma unroll
        for (int kc = 0; kc < 4; kc++) {
            int k0 = kc * 8;
            uint32_t af[4];
            af[0] = Qs[q0 * AP16 + k0 + tg];
            af[1] = Qs[(q0 + 8) * AP16 + k0 + tg];
            af[2] = Qs[q0 * AP16 + k0 + 4 + tg];
            af[3] = Qs[(q0 + 8) * AP16 + k0 + 4 + tg];
            #pragma unroll
            for (int nt = 0; nt < 8; nt++) {
                uint32_t bf[2];
                bf[0] = Ks[(nt * 8 + g) * AP16 + k0 + tg];
                bf[1] = Ks[(nt * 8 + g) * AP16 + k0 + 4 + tg];
                mma_f16(sacc[nt], af, bf);
            }
        }

        // ---- scale + mask + online softmax on fragments ----
        const float* mk0 = mrow0 + kt * KTILE;
        const float* mk1 = mrow1 + kt * KTILE;
        float rm0 = -1e30f, rm1 = -1e30f;
        #pragma unroll
        for (int nt = 0; nt < 8; nt++) {
            float2 a0 = *(const float2*)(mk0 + nt * 8 + 2 * tg);
            float2 a1 = *(const float2*)(mk1 + nt * 8 + 2 * tg);
            sacc[nt][0] = sacc[nt][0] * 0.125f + (a0.x - 1.f) * 1e9f;
            sacc[nt][1] = sacc[nt][1] * 0.125f + (a0.y - 1.f) * 1e9f;
            sacc[nt][2] = sacc[nt][2] * 0.125f + (a1.x - 1.f) * 1e9f;
            sacc[nt][3] = sacc[nt][3] * 0.125f + (a1.y - 1.f) * 1e9f;
            rm0 = fmaxf(rm0, fmaxf(sacc[nt][0], sacc[nt][1]));
            rm1 = fmaxf(rm1, fmaxf(sacc[nt][2], sacc[nt][3]));
        }
        rm0 = fmaxf(rm0, __shfl_xor_sync(0xffffffffu, rm0, 1));
        rm0 = fmaxf(rm0, __shfl_xor_sync(0xffffffffu, rm0, 2));
        rm1 = fmaxf(rm1, __shfl_xor_sync(0xffffffffu, rm1, 1));
        rm1 = fmaxf(rm1, __shfl_xor_sync(0xffffffffu, rm1, 2));

        float mn0 = fmaxf(m0, rm0), mn1 = fmaxf(m1, rm1);
        float corr0 = __expf(m0 - mn0), corr1 = __expf(m1 - mn1);
        m0 = mn0; m1 = mn1;

        float rl0 = 0.f, rl1 = 0.f;
        #pragma unroll
        for (int nt = 0; nt < 8; nt++) {
            float p0 = __expf(sacc[nt][0] - mn0);
            float p1 = __expf(sacc[nt][1] - mn0);
            float p2 = __expf(sacc[nt][2] - mn1);
            float p3 = __expf(sacc[nt][3] - mn1);
            rl0 += p0 + p1;
            rl1 += p2 + p3;
            Ps[q0 * AP16 + nt * 4 + tg]       = packh2(p0, p1);
            Ps[(q0 + 8) * AP16 + nt * 4 + tg] = packh2(p2, p3);
        }
        rl0 += __shfl_xor_sync(0xffffffffu, rl0, 1);
        rl0 += __shfl_xor_sync(0xffffffffu, rl0, 2);
        rl1 += __shfl_xor_sync(0xffffffffu, rl1, 1);
        rl1 += __shfl_xor_sync(0xffffffffu, rl1, 2);
        l0 = l0 * corr0 + rl0;
        l1 = l1 * corr1 + rl1;

        #pragma unroll
        for (int dt = 0; dt < 8; dt++) {
            oacc[dt][0] *= corr0; oacc[dt][1] *= corr0;
            oacc[dt][2] *= corr1; oacc[dt][3] *= corr1;
        }
        __syncwarp();

        // ---- O += P @ V  (A = Ps rows, B = Vt[d][s]) ----
        #pragma unroll
        for (int kc = 0; kc < 4; kc++) {
            int k0 = kc * 8;
            uint32_t af[4];
            af[0] = Ps[q0 * AP16 + k0 + tg];
            af[1] = Ps[(q0 + 8) * AP16 + k0 + tg];
            af[2] = Ps[q0 * AP16 + k0 + 4 + tg];
            af[3] = Ps[(q0 + 8) * AP16 + k0 + 4 + tg];
            #pragma unroll
            for (int dt = 0; dt < 8; dt++) {
                uint32_t bf[2];
                bf[0] = Vt[(dt * 8 + g) * AP16 + k0 + tg];
                bf[1] = Vt[(dt * 8 + g) * AP16 + k0 + 4 + tg];
                mma_f16(oacc[dt], af, bf);
            }
        }
        __syncthreads();
    }

    // ---- epilogue: divide by l, write out ----
    float inv0 = 1.0f / l0, inv1 = 1.0f / l1;
    float* optr = O + ((size_t)(b * TT) + qt * QTILE + w * 16 + g) * DD + h * 64;
    #pragma unroll
    for (int dt = 0; dt < 8; dt++) {
        int col = dt * 8 + 2 * tg;
        *(float2*)(optr + col) =
            make_float2(oacc[dt][0] * inv0, oacc[dt][1] * inv0);
        *(float2*)(optr + 8 * DD + col) =
            make_float2(oacc[dt][2] * inv1, oacc[dt][3] * inv1);
    }
}

// ---------------- launch ----------------
extern "C" void kernel_launch(void* const* d_in, const int* in_sizes, int n_in,
                              void* d_out, int out_size)
{
    const float* x       = (const float*)d_in[0];
    const float* mask    = (const float*)d_in[1];
    const float* ln_in_g = (const float*)d_in[2];
    const float* ln_in_b = (const float*)d_in[3];
    const float* Wq = (const float*)d_in[4];
    const float* bq = (const float*)d_in[5];
    const float* Wk = (const float*)d_in[6];
    const float* bk = (const float*)d_in[7];
    const float* Wv = (const float*)d_in[8];
    const float* bv = (const float*)d_in[9];
    const float* ln1_g = (const float*)d_in[10];
    const float* ln1_b = (const float*)d_in[11];
    const float* W1 = (const float*)d_in[12];
    const float* b1 = (const float*)d_in[13];
    const float* W2 = (const float*)d_in[14];
    const float* b2 = (const float*)d_in[15];
    const float* ln2_g = (const float*)d_in[16];
    const float* ln2_b = (const float*)d_in[17];
    float* out = (float*)d_out;

    __half *h16, *qkv16, *a16, *f116, *wqkvt, *w1t, *w2t;
    float *attnbuf, *abuf, *f2buf, *bqkv;
    cudaGetSymbolAddress((void**)&h16,     g_h16);
    cudaGetSymbolAddress((void**)&qkv16,   g_qkv16);
    cudaGetSymbolAddress((void**)&attnbuf, g_attn);
    cudaGetSymbolAddress((void**)&abuf,    g_a);
    cudaGetSymbolAddress((void**)&a16,     g_a16);
    cudaGetSymbolAddress((void**)&f116,    g_f116);
    cudaGetSymbolAddress((void**)&f2buf,   g_f2);
    cudaGetSymbolAddress((void**)&wqkvt,   g_Wqkvt16);
    cudaGetSymbolAddress((void**)&w1t,     g_W1t16);
    cudaGetSymbolAddress((void**)&w2t,     g_W2t16);
    cudaGetSymbolAddress((void**)&bqkv,    g_bqkv);

    cudaFuncSetAttribute(attn_tc,
                         cudaFuncAttributeMaxDynamicSharedMemorySize, ATTN_SMEM);
    cudaFuncSetAttribute(tc_gemm16<false, true>,
                         cudaFuncAttributeMaxDynamicSharedMemorySize, GEMM_SMEM);
    cudaFuncSetAttribute(tc_gemm16<true, true>,
                         cudaFuncAttributeMaxDynamicSharedMemorySize, GEMM_SMEM);
    cudaFuncSetAttribute(tc_gemm16<false, false>,
                         cudaFuncAttributeMaxDynamicSharedMemorySize, GEMM_SMEM);

    // fused weight transpose (5 matrices, one launch) + bias concat
    transpose_all<<<2816, dim3(32, 8)>>>(Wq, Wk, Wv, W1, W2, wqkvt, w1t, w2t);
    concat_bias<<<NQKV/256, 256>>>(bq, bk, bv, bqkv);

    // 1. h = LN(x) -> fp16 (feeds QKV GEMM only)
    ln_kernel<false, true><<<MM, 256>>>(x, nullptr, ln_in_g, ln_in_b, nullptr, h16);

    // 2. fused QKV: [M,1536] fp16 = h @ [Wq|Wk|Wv]
    tc_gemm16<false, true><<<dim3(NQKV/128, MM/128), 256, GEMM_SMEM>>>(
        h16, wqkvt, bqkv, qkv16, MM, NQKV, DD);

    // 3. masked flash attention (fp16 tensor cores)
    attn_tc<<<dim3(TT/QTILE, HH, BB), 256, ATTN_SMEM>>>(qkv16, mask, attnbuf);

    // 4. a = LN1(attn + x) -> fp32 (LN2 residual) + fp16 (FFN1 input)
    ln_kernel<true, true><<<MM, 256>>>(attnbuf, x, ln1_g, ln1_b, abuf, a16);

    // 5. FFN: f1 = relu(a@W1+b1) fp16; f2 = f1@W2+b2 fp32
    tc_gemm16<true, true><<<dim3(FF/128, MM/128), 256, GEMM_SMEM>>>(
        a16, w1t, b1, f116, MM, FF, DD);
    tc_gemm16<false, false><<<dim3(DD/128, MM/128), 256, GEMM_SMEM>>>(
        f116, w2t, b2, f2buf, MM, DD, FF);

    // 6. out = LN2(f + a)
    ln_kernel<true, false><<<MM, 256>>>(f2buf, abuf, ln2_g, ln2_b, out, nullptr);
}

// round 12
// speedup vs baseline: 4.5969x; 1.1145x over previous
#include <cuda_runtime.h>
#include <cuda_fp16.h>
#include <cstdint>
#include <math.h>

#define BB 8
#define TT 1024
#define DD 512
#define HH 8
#define FF 2048
#define MM (BB*TT)   // 8192 rows
#define NQKV (3*DD)  // 1536

// ---------------- scratch (allocation-free: __device__ globals) ----------------
__device__ __half g_h16[MM*DD];       // LN(x) in fp16 (feeds QKV GEMM)
__device__ __half g_qkv16[MM*NQKV];   // fused QKV output, fp16
__device__ float  g_attn[MM*DD];      // attention output (pre-residual)
__device__ float  g_a[MM*DD];         // LN1(attn + x) fp32 (LN2 residual)
__device__ __half g_a16[MM*DD];       // LN1 fp16 (feeds FFN1)
__device__ __half g_f116[MM*FF];      // relu(a@W1+b1) fp16 (feeds FFN2)
__device__ float  g_f2[MM*DD];        // f1@W2+b2
__device__ __half g_Wqkvt16[NQKV*DD]; // [1536,512] fp16, rows q|k|v, transposed
__device__ __half g_W1t16[FF*DD];     // [2048,512] fp16
__device__ __half g_W2t16[DD*FF];     // [512,2048] fp16
__device__ float  g_bqkv[NQKV];

// ---------------- helpers ----------------
__device__ __forceinline__ uint32_t s2u(const void* p) {
    uint32_t a;
    asm("{ .reg .u64 t; cvta.to.shared.u64 t, %1; cvt.u32.u64 %0, t; }" : "=r"(a) : "l"(p));
    return a;
}
__device__ __forceinline__ void cp_async16(uint32_t saddr, const void* gaddr) {
    asm volatile("cp.async.ca.shared.global [%0], [%1], 16;" :: "r"(saddr), "l"(gaddr));
}
__device__ __forceinline__ void cp_commit() {
    asm volatile("cp.async.commit_group;" ::: "memory");
}
__device__ __forceinline__ void cp_wait1() {
    asm volatile("cp.async.wait_group 1;" ::: "memory");
}
__device__ __forceinline__ void cp_wait0() {
    asm volatile("cp.async.wait_group 0;" ::: "memory");
}
// fp16 m16n8k16, fp32 accumulate
__device__ __forceinline__ void mma_f16(float* c, const uint32_t* a, const uint32_t* b) {
    asm volatile(
        "mma.sync.aligned.m16n8k16.row.col.f32.f16.f16.f32 "
        "{%0,%1,%2,%3}, {%4,%5,%6,%7}, {%8,%9}, {%0,%1,%2,%3};"
        : "+f"(c[0]), "+f"(c[1]), "+f"(c[2]), "+f"(c[3])
        : "r"(a[0]), "r"(a[1]), "r"(a[2]), "r"(a[3]), "r"(b[0]), "r"(b[1]));
}
__device__ __forceinline__ uint32_t packh2(float a, float b) {
    __half2 h = __floats2half2_rn(a, b);
    return *(uint32_t*)&h;
}

// ---------------- fused weight transpose + fp16: all 5 matrices in one launch ---
__global__ void transpose_all(const float* __restrict__ Wq, const float* __restrict__ Wk,
                              const float* __restrict__ Wv, const float* __restrict__ W1,
                              const float* __restrict__ W2,
                              __half* __restrict__ wqkvt, __half* __restrict__ w1t,
                              __half* __restrict__ w2t)
{
    __shared__ float tile[32][33];
    int bid = blockIdx.x;
    const float* W; __half* Wt; int R, N, tl;
    if (bid < 256)       { W = Wq; Wt = wqkvt;             R = DD; N = DD; tl = bid; }
    else if (bid < 512)  { W = Wk; Wt = wqkvt + DD*DD;     R = DD; N = DD; tl = bid - 256; }
    else if (bid < 768)  { W = Wv; Wt = wqkvt + 2*DD*DD;   R = DD; N = DD; tl = bid - 512; }
    else if (bid < 1792) { W = W1; Wt = w1t;               R = DD; N = FF; tl = bid - 768; }
    else                 { W = W2; Wt = w2t;               R = FF; N = DD; tl = bid - 1792; }
    int ntx = N / 32;
    int nb = (tl % ntx) * 32, rb = (tl / ntx) * 32;
    int tx = threadIdx.x, ty = threadIdx.y;   // 32 x 8
    #pragma unroll
    for (int i = 0; i < 32; i += 8)
        tile[ty + i][tx] = W[(size_t)(rb + ty + i) * N + nb + tx];
    __syncthreads();
    #pragma unroll
    for (int i = 0; i < 32; i += 8)
        Wt[(size_t)(nb + ty + i) * R + rb + tx] = __float2half_rn(tile[tx][ty + i]);
}

__global__ void concat_bias(const float* __restrict__ bq, const float* __restrict__ bk,
                            const float* __restrict__ bv, float* __restrict__ o) {
    int t = blockIdx.x * 256 + threadIdx.x;
    if (t < NQKV)
        o[t] = t < 512 ? bq[t] : (t < 1024 ? bk[t - 512] : bv[t - 1024]);
}

// ---------------- fp16 mma GEMM: C[M,N] = A[M,K] @ Bt[N,K]^T + bias -------------
// 128x128 CTA tile, KC=64 halfs, 2-stage cp.async, 256 threads, 2 CTAs/SM.
#define KC16 64
#define P32 36                              // b32 pitch per row
#define STG_HALFS (2 * 128 * 2 * P32)
#define STG_BYTES (STG_HALFS * 2)           // 36864 B
#define GEMM_SMEM (2 * STG_BYTES)           // 73728 B

template<bool RELU, bool OUTHALF>
__global__ __launch_bounds__(256, 2)
void tc_gemm16(const __half* __restrict__ A, const __half* __restrict__ Bt,
               const float* __restrict__ bias, void* __restrict__ Cout,
               int M, int N, int K)
{
    extern __shared__ __half smh[];
    uint32_t sbase = s2u(smh);

    int t = threadIdx.x;
    int wid = t >> 5, lane = t & 31;
    int g = lane >> 2, tg = lane & 3;
    int wm = wid & 1, wn = wid >> 1;
    int brow = blockIdx.y * 128, bcol = blockIdx.x * 128;

    float acc[4][4][4];
    #pragma unroll
    for (int i = 0; i < 4; i++)
        #pragma unroll
        for (int j = 0; j < 4; j++)
            #pragma unroll
            for (int r = 0; r < 4; r++) acc[i][j][r] = 0.f;

    int nk = K / KC16;

    auto load_stage = [&](int s, int c) {
        uint32_t sA = sbase + (uint32_t)s * STG_BYTES;
        uint32_t sB = sA + 128u * P32 * 4u;
        const __half* ag = A + (size_t)brow * K + c * KC16;
        const __half* bg = Bt + (size_t)bcol * K + c * KC16;
        #pragma unroll
        for (int i = 0; i < 4; i++) {
            int idx = t + i * 256;
            int r = idx >> 3, cg = idx & 7;
            cp_async16(sA + (uint32_t)(r * 144 + cg * 16),
                       ag + (size_t)r * K + cg * 8);
            cp_async16(sB + (uint32_t)(r * 144 + cg * 16),
                       bg + (size_t)r * K + cg * 8);
        }
        cp_commit();
    };

    load_stage(0, 0);

    for (int c = 0; c < nk; c++) {
        if (c + 1 < nk) load_stage((c + 1) & 1, c + 1);
        if (c + 1 < nk) cp_wait1(); else cp_wait0();
        __syncthreads();

        const uint32_t* As32 = (const uint32_t*)(smh + (size_t)(c & 1) * STG_HALFS);
        const uint32_t* Bs32 = As32 + 128 * P32;

        #pragma unroll
        for (int ks = 0; ks < 4; ks++) {
            int k0 = ks * 8;
            uint32_t af[4][4], bf[4][2];
            #pragma unroll
            for (int mt = 0; mt < 4; mt++) {
                int r0 = wm * 64 + mt * 16 + g;
                af[mt][0] = As32[r0 * P32 + k0 + tg];
                af[mt][1] = As32[(r0 + 8) * P32 + k0 + tg];
                af[mt][2] = As32[r0 * P32 + k0 + 4 + tg];
                af[mt][3] = As32[(r0 + 8) * P32 + k0 + 4 + tg];
            }
            #pragma unroll
            for (int nt = 0; nt < 4; nt++) {
                int n0 = wn * 32 + nt * 8 + g;
                bf[nt][0] = Bs32[n0 * P32 + k0 + tg];
                bf[nt][1] = Bs32[n0 * P32 + k0 + 4 + tg];
            }
            #pragma unroll
            for (int mt = 0; mt < 4; mt++)
                #pragma unroll
                for (int nt = 0; nt < 4; nt++)
                    mma_f16(acc[mt][nt], af[mt], bf[nt]);
        }
        __syncthreads();
    }

    #pragma unroll
    for (int mt = 0; mt < 4; mt++) {
        int r0 = brow + wm * 64 + mt * 16 + g;
        #pragma unroll
        for (int nt = 0; nt < 4; nt++) {
            int col = bcol + wn * 32 + nt * 8 + tg * 2;
            float2 bv2 = *(const float2*)(bias + col);
            float v0 = acc[mt][nt][0] + bv2.x;
            float v1 = acc[mt][nt][1] + bv2.y;
            float v2 = acc[mt][nt][2] + bv2.x;
            float v3 = acc[mt][nt][3] + bv2.y;
            if (RELU) {
                v0 = fmaxf(v0, 0.f); v1 = fmaxf(v1, 0.f);
                v2 = fmaxf(v2, 0.f); v3 = fmaxf(v3, 0.f);
            }
            if (OUTHALF) {
                __half* C16 = (__half*)Cout;
                *(__half2*)(C16 + (size_t)r0 * N + col) =
                    __floats2half2_rn(v0, v1);
                *(__half2*)(C16 + (size_t)(r0 + 8) * N + col) =
                    __floats2half2_rn(v2, v3);
            } else {
                float* C = (float*)Cout;
                *(float2*)(C + (size_t)r0 * N + col)       = make_float2(v0, v1);
                *(float2*)(C + (size_t)(r0 + 8) * N + col) = make_float2(v2, v3);
            }
        }
    }
}

// ---------------- LayerNorm (fused residual; fp32 and/or fp16 outputs) ----------
template<bool W32, bool W16>
__global__ __launch_bounds__(256) void ln_kernel(
    const float* __restrict__ in1, const float* __restrict__ in2,
    const float* __restrict__ gam, const float* __restrict__ bet,
    float* __restrict__ out32, __half* __restrict__ out16)
{
    int row = blockIdx.x;
    int t = threadIdx.x;
    const float* p1 = in1 + (size_t)row * DD;
    float v0 = p1[t];
    float v1 = p1[t + 256];
    if (in2) {
        const float* p2 = in2 + (size_t)row * DD;
        v0 += p2[t];
        v1 += p2[t + 256];
    }
    __shared__ float red[8];
    float s = v0 + v1;
    #pragma unroll
    for (int o = 16; o > 0; o >>= 1) s += __shfl_xor_sync(0xffffffffu, s, o);
    if ((t & 31) == 0) red[t >> 5] = s;
    __syncthreads();
    float tot = 0.f;
    #pragma unroll
    for (int i = 0; i < 8; i++) tot += red[i];
    float mu = tot * (1.0f / DD);
    float d0 = v0 - mu, d1 = v1 - mu;
    s = d0 * d0 + d1 * d1;
    #pragma unroll
    for (int o = 16; o > 0; o >>= 1) s += __shfl_xor_sync(0xffffffffu, s, o);
    __syncthreads();
    if ((t & 31) == 0) red[t >> 5] = s;
    __syncthreads();
    tot = 0.f;
    #pragma unroll
    for (int i = 0; i < 8; i++) tot += red[i];
    float r = rsqrtf(tot * (1.0f / DD) + 1e-3f);
    float o0 = d0 * r * gam[t]       + bet[t];
    float o1 = d1 * r * gam[t + 256] + bet[t + 256];
    if (W32) {
        out32[(size_t)row * DD + t]       = o0;
        out32[(size_t)row * DD + t + 256] = o1;
    }
    if (W16) {
        out16[(size_t)row * DD + t]       = __float2half_rn(o0);
        out16[(size_t)row * DD + t + 256] = __float2half_rn(o1);
    }
}

// ---------------- tensor-core flash attention (fp16 mma m16n8k16) ---------------
// CTA: 128 queries x 64 keys, DK=64, 256 threads, 2 CTAs/SM.
#define QTILE 128
#define KTILE 64
#define AP16 36   // b32 pitch = 72 halfs
#define ATTN_SMEM ((QTILE + KTILE + KTILE + QTILE) * AP16 * 4)   // 55296 B

__global__ __launch_bounds__(256, 2) void attn_tc(
    const __half* __restrict__ QKV, const float* __restrict__ mask,
    float* __restrict__ O)
{
    extern __shared__ uint32_t sm32[];
    uint32_t* Qs = sm32;                     // [128][36] b32 (rows q, k-pairs)
    uint32_t* Ks = Qs + QTILE * AP16;        // [64][36]  (rows k, d-pairs)
    uint32_t* Vt = Ks + KTILE * AP16;        // [64][36]  (rows d, s-pairs) transposed
    uint32_t* Ps = Vt + KTILE * AP16;        // [128][36] (rows q, s-pairs)

    int b = blockIdx.z, h = blockIdx.y, qt = blockIdx.x;
    int t = threadIdx.x;
    int w = t >> 5, lane = t & 31;
    int g = lane >> 2, tg = lane & 3;

    const __half* qptr  = QKV + ((size_t)(b * TT) + qt * QTILE) * NQKV + h * 64;
    const __half* kptr0 = QKV + (size_t)(b * TT) * NQKV + h * 64 + 512;
    const __half* vptr0 = QKV + (size_t)(b * TT) * NQKV + h * 64 + 1024;

    // load Q tile fp16
    #pragma unroll
    for (int i = 0; i < 4; i++) {
        int idx = t + i * 256;
        int r = idx >> 3, c = idx & 7;
        uint4 raw = *(const uint4*)(qptr + (size_t)r * NQKV + c * 8);
        *(uint4*)&Qs[r * AP16 + c * 4] = raw;
    }

    float m0 = -1e30f, m1 = -1e30f, l0 = 0.f, l1 = 0.f;
    float oacc[8][4];
    #pragma unroll
    for (int dt = 0; dt < 8; dt++)
        #pragma unroll
        for (int r = 0; r < 4; r++) oacc[dt][r] = 0.f;

    const float* mrow0 = mask + ((size_t)b * TT + qt * QTILE + w * 16 + g) * TT;
    const float* mrow1 = mrow0 + 8 * TT;
    int q0 = w * 16 + g;

    for (int kt = 0; kt < TT / KTILE; kt++) {
        // ---- load K (rows k, cols d) ----
        #pragma unroll
        for (int i = 0; i < 2; i++) {
            int idx = t + i * 256;
            int r = idx >> 3, c = idx & 7;
            uint4 raw = *(const uint4*)(kptr0 + (size_t)(kt * KTILE + r) * NQKV + c * 8);
            *(uint4*)&Ks[r * AP16 + c * 4] = raw;
        }
        // ---- load V transposed: Vt[d][s] ----
        #pragma unroll
        for (int i = 0; i < 4; i++) {
            int idx = t + i * 256;
            int d = idx & 63, s0 = (idx >> 6) * 4;
            const __half* vp = vptr0 + (size_t)(kt * KTILE + s0) * NQKV + d;
            __half2 lo = __halves2half2(vp[0], vp[NQKV]);
            __half2 hi = __halves2half2(vp[2 * NQKV], vp[3 * NQKV]);
            uint2 pk;
            pk.x = *(uint32_t*)&lo; pk.y = *(uint32_t*)&hi;
            *(uint2*)&Vt[d * AP16 + (s0 >> 1)] = pk;
        }
        __syncthreads();

        // ---- S = Q K^T ----
        float sacc[8][4];
        #pragma unroll
        for (int nt = 0; nt < 8; nt++)
            #pragma unroll
            for (int r = 0; r < 4; r++) sacc[nt][r] = 0.f;

        #pragma unroll
        for (int kc = 0; kc < 4; kc++) {
            int k0 = kc * 8;
            uint32_t af[4];
            af[0] = Qs[q0 * AP16 + k0 + tg];
            af[1] = Qs[(q0 + 8) * AP16 + k0 + tg];
            af[2] = Qs[q0 * AP16 + k0 + 4 + tg];
            af[3] = Qs[(q0 + 8) * AP16 + k0 + 4 + tg];
            #pragma unroll
            for (int nt = 0; nt < 8; nt++) {
                uint32_t bf[2];
                bf[0] = Ks[(nt * 8 + g) * AP16 + k0 + tg];
                bf[1] = Ks[(nt * 8 + g) * AP16 + k0 + 4 + tg];
                mma_f16(sacc[nt], af, bf);
            }
        }

        // ---- scale + mask + online softmax on fragments ----
        const float* mk0 = mrow0 + kt * KTILE;
        const float* mk1 = mrow1 + kt * KTILE;
        float rm0 = -1e30f, rm1 = -1e30f;
        #pragma unroll
        for (int nt = 0; nt < 8; nt++) {
            float2 a0 = *(const float2*)(mk0 + nt * 8 + 2 * tg);
            float2 a1 = *(const float2*)(mk1 + nt * 8 + 2 * tg);
            sacc[nt][0] = sacc[nt][0] * 0.125f + (a0.x - 1.f) * 1e9f;
            sacc[nt][1] = sacc[nt][1] * 0.125f + (a0.y - 1.f) * 1e9f;
            sacc[nt][2] = sacc[nt][2] * 0.125f + (a1.x - 1.f) * 1e9f;
            sacc[nt][3] = sacc[nt][3] * 0.125f + (a1.y - 1.f) * 1e9f;
            rm0 = fmaxf(rm0, fmaxf(sacc[nt][0], sacc[nt][1]));
            rm1 = fmaxf(rm1, fmaxf(sacc[nt][2], sacc[nt][3]));
        }
        rm0 = fmaxf(rm0, __shfl_xor_sync(0xffffffffu, rm0, 1));
        rm0 = fmaxf(rm0, __shfl_xor_sync(0xffffffffu, rm0, 2));
        rm1 = fmaxf(rm1, __shfl_xor_sync(0xffffffffu, rm1, 1));
        rm1 = fmaxf(rm1, __shfl_xor_sync(0xffffffffu, rm1, 2));

        float mn0 = fmaxf(m0, rm0), mn1 = fmaxf(m1, rm1);
        float corr0 = __expf(m0 - mn0), corr1 = __expf(m1 - mn1);
        m0 = mn0; m1 = mn1;

        float rl0 = 0.f, rl1 = 0.f;
        #pragma unroll
        for (int nt = 0; nt < 8; nt++) {
            float p0 = __expf(sacc[nt][0] - mn0);
            float p1 = __expf(sacc[nt][1] - mn0);
            float p2 = __expf(sacc[nt][2] - mn1);
            float p3 = __expf(sacc[nt][3] - mn1);
            rl0 += p0 + p1;
            rl1 += p2 + p3;
            Ps[q0 * AP16 + nt * 4 + tg]       = packh2(p0, p1);
            Ps[(q0 + 8) * AP16 + nt * 4 + tg] = packh2(p2, p3);
        }
        rl0 += __shfl_xor_sync(0xffffffffu, rl0, 1);
        rl0 += __shfl_xor_sync(0xffffffffu, rl0, 2);
        rl1 += __shfl_xor_sync(0xffffffffu, rl1, 1);
        rl1 += __shfl_xor_sync(0xffffffffu, rl1, 2);
        l0 = l0 * corr0 + rl0;
        l1 = l1 * corr1 + rl1;

        #pragma unroll
        for (int dt = 0; dt < 8; dt++) {
            oacc[dt][0] *= corr0; oacc[dt][1] *= corr0;
            oacc[dt][2] *= corr1; oacc[dt][3] *= corr1;
        }
        __syncwarp();

        // ---- O += P @ V ----
        #pragma unroll
        for (int kc = 0; kc < 4; kc++) {
            int k0 = kc * 8;
            uint32_t af[4];
            af[0] = Ps[q0 * AP16 + k0 + tg];
            af[1] = Ps[(q0 + 8) * AP16 + k0 + tg];
            af[2] = Ps[q0 * AP16 + k0 + 4 + tg];
            af[3] = Ps[(q0 + 8) * AP16 + k0 + 4 + tg];
            #pragma unroll
            for (int dt = 0; dt < 8; dt++) {
                uint32_t bf[2];
                bf[0] = Vt[(dt * 8 + g) * AP16 + k0 + tg];
                bf[1] = Vt[(dt * 8 + g) * AP16 + k0 + 4 + tg];
                mma_f16(oacc[dt], af, bf);
            }
        }
        __syncthreads();
    }

    // ---- epilogue ----
    float inv0 = 1.0f / l0, inv1 = 1.0f / l1;
    float* optr = O + ((size_t)(b * TT) + qt * QTILE + w * 16 + g) * DD + h * 64;
    #pragma unroll
    for (int dt = 0; dt < 8; dt++) {
        int col = dt * 8 + 2 * tg;
        *(float2*)(optr + col) =
            make_float2(oacc[dt][0] * inv0, oacc[dt][1] * inv0);
        *(float2*)(optr + 8 * DD + col) =
            make_float2(oacc[dt][2] * inv1, oacc[dt][3] * inv1);
    }
}

// ---------------- launch ----------------
extern "C" void kernel_launch(void* const* d_in, const int* in_sizes, int n_in,
                              void* d_out, int out_size)
{
    const float* x       = (const float*)d_in[0];
    const float* mask    = (const float*)d_in[1];
    const float* ln_in_g = (const float*)d_in[2];
    const float* ln_in_b = (const float*)d_in[3];
    const float* Wq = (const float*)d_in[4];
    const float* bq = (const float*)d_in[5];
    const float* Wk = (const float*)d_in[6];
    const float* bk = (const float*)d_in[7];
    const float* Wv = (const float*)d_in[8];
    const float* bv = (const float*)d_in[9];
    const float* ln1_g = (const float*)d_in[10];
    const float* ln1_b = (const float*)d_in[11];
    const float* W1 = (const float*)d_in[12];
    const float* b1 = (const float*)d_in[13];
    const float* W2 = (const float*)d_in[14];
    const float* b2 = (const float*)d_in[15];
    const float* ln2_g = (const float*)d_in[16];
    const float* ln2_b = (const float*)d_in[17];
    float* out = (float*)d_out;

    __half *h16, *qkv16, *a16, *f116, *wqkvt, *w1t, *w2t;
    float *attnbuf, *abuf, *f2buf, *bqkv;
    cudaGetSymbolAddress((void**)&h16,     g_h16);
    cudaGetSymbolAddress((void**)&qkv16,   g_qkv16);
    cudaGetSymbolAddress((void**)&attnbuf, g_attn);
    cudaGetSymbolAddress((void**)&abuf,    g_a);
    cudaGetSymbolAddress((void**)&a16,     g_a16);
    cudaGetSymbolAddress((void**)&f116,    g_f116);
    cudaGetSymbolAddress((void**)&f2buf,   g_f2);
    cudaGetSymbolAddress((void**)&wqkvt,   g_Wqkvt16);
    cudaGetSymbolAddress((void**)&w1t,     g_W1t16);
    cudaGetSymbolAddress((void**)&w2t,     g_W2t16);
    cudaGetSymbolAddress((void**)&bqkv,    g_bqkv);

    cudaFuncSetAttribute(attn_tc,
                         cudaFuncAttributeMaxDynamicSharedMemorySize, ATTN_SMEM);
    cudaFuncSetAttribute(tc_gemm16<false, true>,
                         cudaFuncAttributeMaxDynamicSharedMemorySize, GEMM_SMEM);
    cudaFuncSetAttribute(tc_gemm16<true, true>,
                         cudaFuncAttributeMaxDynamicSharedMemorySize, GEMM_SMEM);
    cudaFuncSetAttribute(tc_gemm16<false, false>,
                         cudaFuncAttributeMaxDynamicSharedMemorySize, GEMM_SMEM);

    // fused weight transpose (5 matrices, one launch) + bias concat
    transpose_all<<<2816, dim3(32, 8)>>>(Wq, Wk, Wv, W1, W2, wqkvt, w1t, w2t);
    concat_bias<<<NQKV/256, 256>>>(bq, bk, bv, bqkv);

    // 1. h = LN(x) -> fp16 (feeds QKV GEMM only)
    ln_kernel<false, true><<<MM, 256>>>(x, nullptr, ln_in_g, ln_in_b, nullptr, h16);

    // 2. fused QKV: [M,1536] fp16 = h @ [Wq|Wk|Wv]
    tc_gemm16<false, true><<<dim3(NQKV/128, MM/128), 256, GEMM_SMEM>>>(
        h16, wqkvt, bqkv, qkv16, MM, NQKV, DD);

    // 3. masked flash attention (fp16 tensor cores)
    attn_tc<<<dim3(TT/QTILE, HH, BB), 256, ATTN_SMEM>>>(qkv16, mask, attnbuf);

    // 4. a = LN1(attn + x) -> fp32 (LN2 residual) + fp16 (FFN1 input)
    ln_kernel<true, true><<<MM, 256>>>(attnbuf, x, ln1_g, ln1_b, abuf, a16);

    // 5. FFN: f1 = relu(a@W1+b1) fp16; f2 = f1@W2+b2 fp32
    tc_gemm16<true, true><<<dim3(FF/128, MM/128), 256, GEMM_SMEM>>>(
        a16, w1t, b1, f116, MM, FF, DD);
    tc_gemm16<false, false><<<dim3(DD/128, MM/128), 256, GEMM_SMEM>>>(
        f116, w2t, b2, f2buf, MM, DD, FF);

    // 6. out = LN2(f + a)
    ln_kernel<true, false><<<MM, 256>>>(f2buf, abuf, ln2_g, ln2_b, out, nullptr);
}